// round 1
// baseline (speedup 1.0000x reference)
#include <cuda_runtime.h>
#include <math.h>

// ---------------------------------------------------------------------------
// Problem constants
//   B=32, N1=2048, DIM=1024, HEADS=16, DH=64, NQ=64, L=2, FF=4096
//   NCAT = N1 + NQ = 2112, MCAT = B*NCAT = 67584, MLAT = B*NQ = 2048
// ---------------------------------------------------------------------------

#define F_RES  1
#define F_BIAS 2
#define F_GELU 4

// Scratch (device globals: allocation-free rule)
__device__ float g_xcat[69206016];   // 32*2112*1024   (LN(x) ++ LN(lat) concatenated)
__device__ float g_kv  [138412032];  // 32*2112*2048   (K | V)
__device__ float g_lat [2097152];    // 32*64*1024
__device__ float g_ltn [2097152];
__device__ float g_q   [2097152];
__device__ float g_o   [2097152];
__device__ float g_h   [8388608];    // 2048*4096 FFN hidden
__device__ float g_t2  [2097152];

// ---------------------------------------------------------------------------
// latents broadcast: lat[b*64+l, :] = latents[l, :]
// ---------------------------------------------------------------------------
__global__ void bcast_kernel(const float* __restrict__ lat0, float* __restrict__ lat)
{
    int i = blockIdx.x * 256 + threadIdx.x;       // 0 .. 2048*1024-1
    lat[i] = lat0[i & 65535];                     // 64*1024 = 65536 per batch
}

// ---------------------------------------------------------------------------
// LayerNorm over 1024 cols. 256 threads, 4 elems/thread (float4).
// Output row remap: orow = (r / rpb) * obs + obase + (r % rpb)
// ---------------------------------------------------------------------------
__global__ void ln_kernel(const float* __restrict__ in, float* __restrict__ out,
                          const float* __restrict__ gs, const float* __restrict__ gb,
                          int rpb, int obs, int obase)
{
    __shared__ float red[9];
    int r = blockIdx.x;
    long orow = (long)(r / rpb) * obs + obase + (r % rpb);
    int tid = threadIdx.x;

    const float4 xv = ((const float4*)(in + (size_t)r * 1024))[tid];

    // pass 1: mean
    float s = xv.x + xv.y + xv.z + xv.w;
    #pragma unroll
    for (int o = 16; o; o >>= 1) s += __shfl_xor_sync(0xffffffffu, s, o);
    if ((tid & 31) == 0) red[tid >> 5] = s;
    __syncthreads();
    if (tid == 0) {
        float t = 0.f;
        #pragma unroll
        for (int i = 0; i < 8; i++) t += red[i];
        red[8] = t * (1.0f / 1024.0f);
    }
    __syncthreads();
    float mean = red[8];
    __syncthreads();

    // pass 2: variance
    float dx = xv.x - mean, dy = xv.y - mean, dz = xv.z - mean, dw = xv.w - mean;
    float sq = dx*dx + dy*dy + dz*dz + dw*dw;
    #pragma unroll
    for (int o = 16; o; o >>= 1) sq += __shfl_xor_sync(0xffffffffu, sq, o);
    if ((tid & 31) == 0) red[tid >> 5] = sq;
    __syncthreads();
    if (tid == 0) {
        float t = 0.f;
        #pragma unroll
        for (int i = 0; i < 8; i++) t += red[i];
        red[8] = rsqrtf(t * (1.0f / 1024.0f) + 1e-5f);
    }
    __syncthreads();
    float inv = red[8];

    const float4 sv = ((const float4*)gs)[tid];
    const float4 bv = ((const float4*)gb)[tid];
    float4 ov;
    ov.x = dx * inv * sv.x + bv.x;
    ov.y = dy * inv * sv.y + bv.y;
    ov.z = dz * inv * sv.z + bv.z;
    ov.w = dw * inv * sv.w + bv.w;
    ((float4*)(out + orow * 1024))[tid] = ov;
}

// ---------------------------------------------------------------------------
// FP32 SGEMM: C[M,N] = A[M,K] @ B[K,N]  (+epilogue)
// 128x128 block tile, BK=16, 256 threads, 8x8 per thread.
// M % 128 == 0, N % 128 == 0, K % 16 == 0 assumed (holds for all call sites).
// ---------------------------------------------------------------------------
__device__ __forceinline__ float gelu_f(float x)
{
    float x3 = x * x * x;
    return 0.5f * x * (1.0f + tanhf(0.7978845608028654f * (x + 0.044715f * x3)));
}

__global__ __launch_bounds__(256) void sgemm_kernel(
    const float* __restrict__ A, const float* __restrict__ B,
    const float* __restrict__ Cin, const float* __restrict__ bias,
    float* __restrict__ C, int M, int N, int K, int flags)
{
    __shared__ __align__(16) float As[16][128];
    __shared__ __align__(16) float Bs[16][128];

    const int tid = threadIdx.x;
    const long rowBase = (long)blockIdx.y * 128;
    const long colBase = (long)blockIdx.x * 128;
    const int tr = (tid >> 4) << 3;   // 0..120
    const int tc = (tid & 15) << 3;

    const int a_r = tid >> 2;         // 0..63 (and +64)
    const int a_c = (tid & 3) << 2;   // 0,4,8,12
    const int b_r = tid >> 5;         // 0..7 (and +8)
    const int b_c = (tid & 31) << 2;  // 0..124

    const float* Ap = A + rowBase * K;
    const float* Bp = B + colBase;

    float acc[8][8];
    #pragma unroll
    for (int i = 0; i < 8; i++)
        #pragma unroll
        for (int j = 0; j < 8; j++) acc[i][j] = 0.f;

    const int ktiles = K >> 4;
    for (int kt = 0; kt < ktiles; kt++) {
        const int k0 = kt << 4;
        float4 a0 = *(const float4*)(Ap + (size_t)a_r        * K + k0 + a_c);
        float4 a1 = *(const float4*)(Ap + (size_t)(a_r + 64) * K + k0 + a_c);
        float4 b0 = *(const float4*)(Bp + (size_t)(k0 + b_r    ) * N + b_c);
        float4 b1 = *(const float4*)(Bp + (size_t)(k0 + b_r + 8) * N + b_c);

        __syncthreads();
        As[a_c + 0][a_r] = a0.x; As[a_c + 1][a_r] = a0.y;
        As[a_c + 2][a_r] = a0.z; As[a_c + 3][a_r] = a0.w;
        As[a_c + 0][a_r + 64] = a1.x; As[a_c + 1][a_r + 64] = a1.y;
        As[a_c + 2][a_r + 64] = a1.z; As[a_c + 3][a_r + 64] = a1.w;
        *(float4*)&Bs[b_r    ][b_c] = b0;
        *(float4*)&Bs[b_r + 8][b_c] = b1;
        __syncthreads();

        #pragma unroll
        for (int kk = 0; kk < 16; kk++) {
            float4 ra0 = *(const float4*)&As[kk][tr];
            float4 ra1 = *(const float4*)&As[kk][tr + 4];
            float4 rb0 = *(const float4*)&Bs[kk][tc];
            float4 rb1 = *(const float4*)&Bs[kk][tc + 4];
            float ra[8] = {ra0.x, ra0.y, ra0.z, ra0.w, ra1.x, ra1.y, ra1.z, ra1.w};
            float rb[8] = {rb0.x, rb0.y, rb0.z, rb0.w, rb1.x, rb1.y, rb1.z, rb1.w};
            #pragma unroll
            for (int i = 0; i < 8; i++)
                #pragma unroll
                for (int j = 0; j < 8; j++)
                    acc[i][j] += ra[i] * rb[j];
        }
    }

    // epilogue
    #pragma unroll
    for (int i = 0; i < 8; i++) {
        long row = rowBase + tr + i;
        float* cp = C + row * N + colBase + tc;
        const float* rp = (flags & F_RES) ? (Cin + row * N + colBase + tc) : nullptr;
        #pragma unroll
        for (int j = 0; j < 8; j++) {
            float v = acc[i][j];
            if (flags & F_BIAS) v += bias[colBase + tc + j];
            if (flags & F_GELU) v = gelu_f(v);
            if (flags & F_RES)  v += rp[j];
            cp[j] = v;
        }
    }
}

// ---------------------------------------------------------------------------
// Attention: one block per (batch, head). NQ=64 queries resident, stream
// 32-key chunks of the 2112-token KV with online softmax.
// Q: [B*64, 1024] (head h at col h*64), KV: [B*2112, 2048] (K|V)
// O: [B*64, 1024]
// ---------------------------------------------------------------------------
__global__ __launch_bounds__(256) void attn_kernel(
    const float* __restrict__ Q, const float* __restrict__ KV, float* __restrict__ O)
{
    const int bh = blockIdx.x;
    const int b  = bh >> 4;
    const int h  = bh & 15;

    __shared__ float qs[64][64];
    __shared__ float ks[32][65];
    __shared__ float vs[32][65];
    __shared__ float Ss[64][33];

    const int tid = threadIdx.x;
    const int r  = tid >> 2;         // query row 0..63
    const int g  = tid & 3;          // sub-lane in 4-group
    const int j0 = g << 3;           // key offset for score phase
    const int d0 = g << 4;           // dim offset for accum phase

    // load q, fold in full softmax scale (64^-0.25)^2 = 0.125
    const float* Qb = Q + ((size_t)b * 64) * 1024 + h * 64;
    for (int i = tid; i < 64 * 64; i += 256) {
        int qr = i >> 6, qd = i & 63;
        qs[qr][qd] = Qb[(size_t)qr * 1024 + qd] * 0.125f;
    }

    float m_r = -1e30f, l_r = 0.f;
    float oacc[16];
    #pragma unroll
    for (int i = 0; i < 16; i++) oacc[i] = 0.f;

    const float* KVb = KV + ((size_t)b * 2112) * 2048;

    for (int c = 0; c < 66; c++) {          // 66 * 32 = 2112
        const int n0 = c << 5;
        __syncthreads();
        for (int i = tid; i < 32 * 64; i += 256) {
            int kr = i >> 6, kd = i & 63;
            const float* row = KVb + (size_t)(n0 + kr) * 2048 + h * 64;
            ks[kr][kd] = row[kd];
            vs[kr][kd] = row[1024 + kd];
        }
        __syncthreads();

        // scores for (row r, keys j0..j0+7)
        float sv[8];
        #pragma unroll
        for (int jj = 0; jj < 8; jj++) {
            float s = 0.f;
            #pragma unroll
            for (int d = 0; d < 64; d++) s += qs[r][d] * ks[j0 + jj][d];
            sv[jj] = s;
        }
        float cm = sv[0];
        #pragma unroll
        for (int jj = 1; jj < 8; jj++) cm = fmaxf(cm, sv[jj]);
        cm = fmaxf(cm, __shfl_xor_sync(0xffffffffu, cm, 1));
        cm = fmaxf(cm, __shfl_xor_sync(0xffffffffu, cm, 2));

        float mnew  = fmaxf(m_r, cm);
        float alpha = __expf(m_r - mnew);
        float ps = 0.f;
        #pragma unroll
        for (int jj = 0; jj < 8; jj++) {
            float p = __expf(sv[jj] - mnew);
            Ss[r][j0 + jj] = p;
            ps += p;
        }
        ps += __shfl_xor_sync(0xffffffffu, ps, 1);
        ps += __shfl_xor_sync(0xffffffffu, ps, 2);
        l_r = l_r * alpha + ps;
        m_r = mnew;
        __syncwarp();

        #pragma unroll
        for (int di = 0; di < 16; di++) oacc[di] *= alpha;
        #pragma unroll 4
        for (int j = 0; j < 32; j++) {
            float p = Ss[r][j];
            #pragma unroll
            for (int di = 0; di < 16; di++)
                oacc[di] += p * vs[j][d0 + di];
        }
        __syncwarp();
    }

    float inv = 1.0f / l_r;
    float* Ob = O + ((size_t)(b * 64 + r)) * 1024 + h * 64 + d0;
    #pragma unroll
    for (int di = 0; di < 16; di++) Ob[di] = oacc[di] * inv;
}

// ---------------------------------------------------------------------------
// Launch
// ---------------------------------------------------------------------------
extern "C" void kernel_launch(void* const* d_in, const int* in_sizes, int n_in,
                              void* d_out, int out_size)
{
    const float* x       = (const float*)d_in[0];
    const float* latents = (const float*)d_in[1];
    const float* n1s     = (const float*)d_in[2];
    const float* n1b     = (const float*)d_in[3];
    const float* n2s     = (const float*)d_in[4];
    const float* n2b     = (const float*)d_in[5];
    const float* Wq      = (const float*)d_in[6];
    const float* Wkv     = (const float*)d_in[7];
    const float* Wo      = (const float*)d_in[8];
    const float* ffs     = (const float*)d_in[9];
    const float* ffb     = (const float*)d_in[10];
    const float* W1      = (const float*)d_in[11];
    const float* W2      = (const float*)d_in[12];
    const float* projw   = (const float*)d_in[13];
    const float* projb   = (const float*)d_in[14];
    const float* outs    = (const float*)d_in[15];
    const float* outb    = (const float*)d_in[16];
    float* out = (float*)d_out;

    float *xcat, *kv, *lat, *ltn, *q, *o, *hbuf, *t2;
    cudaGetSymbolAddress((void**)&xcat, g_xcat);
    cudaGetSymbolAddress((void**)&kv,   g_kv);
    cudaGetSymbolAddress((void**)&lat,  g_lat);
    cudaGetSymbolAddress((void**)&ltn,  g_ltn);
    cudaGetSymbolAddress((void**)&q,    g_q);
    cudaGetSymbolAddress((void**)&o,    g_o);
    cudaGetSymbolAddress((void**)&hbuf, g_h);
    cudaGetSymbolAddress((void**)&t2,   g_t2);

    // lat = broadcast(latents)
    bcast_kernel<<<8192, 256>>>(latents, lat);

    const dim3 gq (1024 / 128, 2048 / 128);    // (8, 16)    N=1024 GEMMs on 2048 rows
    const dim3 gkv(2048 / 128, 67584 / 128);   // (16, 528)  KV GEMM
    const dim3 g1 (4096 / 128, 2048 / 128);    // (32, 16)   FFN up

    for (int i = 0; i < 2; i++) {
        // xn = LN(x) -> xcat rows [b*2112 + 0, 2048)
        ln_kernel<<<65536, 256>>>(x, xcat, n1s + i * 1024, n1b + i * 1024, 2048, 2112, 0);
        // ltn = LN(lat) -> contiguous, and -> xcat rows [b*2112 + 2048, 2112)
        ln_kernel<<<2048, 256>>>(lat, ltn,  n2s + i * 1024, n2b + i * 1024, 2048, 2048, 0);
        ln_kernel<<<2048, 256>>>(lat, xcat, n2s + i * 1024, n2b + i * 1024, 64, 2112, 2048);

        // q = ltn @ Wq[i]
        sgemm_kernel<<<gq, 256>>>(ltn, Wq + (size_t)i * 1048576, nullptr, nullptr,
                                  q, 2048, 1024, 1024, 0);
        // kv = xcat @ Wkv[i]
        sgemm_kernel<<<gkv, 256>>>(xcat, Wkv + (size_t)i * 2097152, nullptr, nullptr,
                                   kv, 67584, 2048, 1024, 0);
        // attention
        attn_kernel<<<512, 256>>>(q, kv, o);
        // lat = lat + o @ Wo[i]
        sgemm_kernel<<<gq, 256>>>(o, Wo + (size_t)i * 1048576, lat, nullptr,
                                  lat, 2048, 1024, 1024, F_RES);
        // h = gelu(LN_ff(lat) @ W1[i])
        ln_kernel<<<2048, 256>>>(lat, ltn, ffs + i * 1024, ffb + i * 1024, 2048, 2048, 0);
        sgemm_kernel<<<g1, 256>>>(ltn, W1 + (size_t)i * 4194304, nullptr, nullptr,
                                  hbuf, 2048, 4096, 1024, F_GELU);
        // lat = lat + h @ W2[i]
        sgemm_kernel<<<gq, 256>>>(hbuf, W2 + (size_t)i * 4194304, lat, nullptr,
                                  lat, 2048, 1024, 4096, F_RES);
    }

    // out = LN(lat @ proj_w + proj_b)
    sgemm_kernel<<<gq, 256>>>(lat, projw, nullptr, projb, t2, 2048, 1024, 1024, F_BIAS);
    ln_kernel<<<2048, 256>>>(t2, out, outs, outb, 2048, 2048, 0);
}

// round 2
// speedup vs baseline: 1.0013x; 1.0013x over previous
#include <cuda_runtime.h>
#include <math.h>

// ---------------------------------------------------------------------------
// Problem constants
//   B=32, N1=2048, DIM=1024, HEADS=16, DH=64, NQ=64, L=2, FF=4096
//   NCAT = N1 + NQ = 2112, MCAT = B*NCAT = 67584, MLAT = B*NQ = 2048
// ---------------------------------------------------------------------------

#define F_RES  1
#define F_BIAS 2
#define F_GELU 4

// Scratch (device globals: allocation-free rule)
__device__ float g_xcat[69206016];   // 32*2112*1024   (LN(x) ++ LN(lat) concatenated)
__device__ float g_kv  [138412032];  // 32*2112*2048   (K | V)
__device__ float g_lat [2097152];    // 32*64*1024
__device__ float g_ltn [2097152];
__device__ float g_q   [2097152];
__device__ float g_o   [2097152];
__device__ float g_h   [8388608];    // 2048*4096 FFN hidden
__device__ float g_t2  [2097152];

// ---------------------------------------------------------------------------
// latents broadcast: lat[b*64+l, :] = latents[l, :]
// ---------------------------------------------------------------------------
__global__ void bcast_kernel(const float* __restrict__ lat0, float* __restrict__ lat)
{
    int i = blockIdx.x * 256 + threadIdx.x;       // 0 .. 2048*1024-1
    lat[i] = lat0[i & 65535];                     // 64*1024 = 65536 per batch
}

// ---------------------------------------------------------------------------
// LayerNorm over 1024 cols. 256 threads, 4 elems/thread (float4).
// Output row remap: orow = (r / rpb) * obs + obase + (r % rpb)
// ---------------------------------------------------------------------------
__global__ void ln_kernel(const float* __restrict__ in, float* __restrict__ out,
                          const float* __restrict__ gs, const float* __restrict__ gb,
                          int rpb, int obs, int obase)
{
    __shared__ float red[9];
    int r = blockIdx.x;
    long orow = (long)(r / rpb) * obs + obase + (r % rpb);
    int tid = threadIdx.x;

    const float4 xv = ((const float4*)(in + (size_t)r * 1024))[tid];

    // pass 1: mean
    float s = xv.x + xv.y + xv.z + xv.w;
    #pragma unroll
    for (int o = 16; o; o >>= 1) s += __shfl_xor_sync(0xffffffffu, s, o);
    if ((tid & 31) == 0) red[tid >> 5] = s;
    __syncthreads();
    if (tid == 0) {
        float t = 0.f;
        #pragma unroll
        for (int i = 0; i < 8; i++) t += red[i];
        red[8] = t * (1.0f / 1024.0f);
    }
    __syncthreads();
    float mean = red[8];
    __syncthreads();

    // pass 2: variance
    float dx = xv.x - mean, dy = xv.y - mean, dz = xv.z - mean, dw = xv.w - mean;
    float sq = dx*dx + dy*dy + dz*dz + dw*dw;
    #pragma unroll
    for (int o = 16; o; o >>= 1) sq += __shfl_xor_sync(0xffffffffu, sq, o);
    if ((tid & 31) == 0) red[tid >> 5] = sq;
    __syncthreads();
    if (tid == 0) {
        float t = 0.f;
        #pragma unroll
        for (int i = 0; i < 8; i++) t += red[i];
        red[8] = rsqrtf(t * (1.0f / 1024.0f) + 1e-5f);
    }
    __syncthreads();
    float inv = red[8];

    const float4 sv = ((const float4*)gs)[tid];
    const float4 bv = ((const float4*)gb)[tid];
    float4 ov;
    ov.x = dx * inv * sv.x + bv.x;
    ov.y = dy * inv * sv.y + bv.y;
    ov.z = dz * inv * sv.z + bv.z;
    ov.w = dw * inv * sv.w + bv.w;
    ((float4*)(out + orow * 1024))[tid] = ov;
}

// ---------------------------------------------------------------------------
// FP32 SGEMM: C[M,N] = A[M,K] @ B[K,N]  (+epilogue)
// 128x128 block tile, BK=16, 256 threads, 8x8 per thread.
// M % 128 == 0, N % 128 == 0, K % 16 == 0 assumed (holds for all call sites).
// ---------------------------------------------------------------------------
__device__ __forceinline__ float gelu_f(float x)
{
    float x3 = x * x * x;
    return 0.5f * x * (1.0f + tanhf(0.7978845608028654f * (x + 0.044715f * x3)));
}

__global__ __launch_bounds__(256) void sgemm_kernel(
    const float* __restrict__ A, const float* __restrict__ B,
    const float* __restrict__ Cin, const float* __restrict__ bias,
    float* __restrict__ C, int M, int N, int K, int flags)
{
    __shared__ __align__(16) float As[16][128];
    __shared__ __align__(16) float Bs[16][128];

    const int tid = threadIdx.x;
    const long rowBase = (long)blockIdx.y * 128;
    const long colBase = (long)blockIdx.x * 128;
    const int tr = (tid >> 4) << 3;   // 0..120
    const int tc = (tid & 15) << 3;

    const int a_r = tid >> 2;         // 0..63 (and +64)
    const int a_c = (tid & 3) << 2;   // 0,4,8,12
    const int b_r = tid >> 5;         // 0..7 (and +8)
    const int b_c = (tid & 31) << 2;  // 0..124

    const float* Ap = A + rowBase * K;
    const float* Bp = B + colBase;

    float acc[8][8];
    #pragma unroll
    for (int i = 0; i < 8; i++)
        #pragma unroll
        for (int j = 0; j < 8; j++) acc[i][j] = 0.f;

    const int ktiles = K >> 4;
    for (int kt = 0; kt < ktiles; kt++) {
        const int k0 = kt << 4;
        float4 a0 = *(const float4*)(Ap + (size_t)a_r        * K + k0 + a_c);
        float4 a1 = *(const float4*)(Ap + (size_t)(a_r + 64) * K + k0 + a_c);
        float4 b0 = *(const float4*)(Bp + (size_t)(k0 + b_r    ) * N + b_c);
        float4 b1 = *(const float4*)(Bp + (size_t)(k0 + b_r + 8) * N + b_c);

        __syncthreads();
        As[a_c + 0][a_r] = a0.x; As[a_c + 1][a_r] = a0.y;
        As[a_c + 2][a_r] = a0.z; As[a_c + 3][a_r] = a0.w;
        As[a_c + 0][a_r + 64] = a1.x; As[a_c + 1][a_r + 64] = a1.y;
        As[a_c + 2][a_r + 64] = a1.z; As[a_c + 3][a_r + 64] = a1.w;
        *(float4*)&Bs[b_r    ][b_c] = b0;
        *(float4*)&Bs[b_r + 8][b_c] = b1;
        __syncthreads();

        #pragma unroll
        for (int kk = 0; kk < 16; kk++) {
            float4 ra0 = *(const float4*)&As[kk][tr];
            float4 ra1 = *(const float4*)&As[kk][tr + 4];
            float4 rb0 = *(const float4*)&Bs[kk][tc];
            float4 rb1 = *(const float4*)&Bs[kk][tc + 4];
            float ra[8] = {ra0.x, ra0.y, ra0.z, ra0.w, ra1.x, ra1.y, ra1.z, ra1.w};
            float rb[8] = {rb0.x, rb0.y, rb0.z, rb0.w, rb1.x, rb1.y, rb1.z, rb1.w};
            #pragma unroll
            for (int i = 0; i < 8; i++)
                #pragma unroll
                for (int j = 0; j < 8; j++)
                    acc[i][j] += ra[i] * rb[j];
        }
    }

    // epilogue
    #pragma unroll
    for (int i = 0; i < 8; i++) {
        long row = rowBase + tr + i;
        float* cp = C + row * N + colBase + tc;
        const float* rp = (flags & F_RES) ? (Cin + row * N + colBase + tc) : nullptr;
        #pragma unroll
        for (int j = 0; j < 8; j++) {
            float v = acc[i][j];
            if (flags & F_BIAS) v += bias[colBase + tc + j];
            if (flags & F_GELU) v = gelu_f(v);
            if (flags & F_RES)  v += rp[j];
            cp[j] = v;
        }
    }
}

// ---------------------------------------------------------------------------
// Attention: one block per (batch, head). NQ=64 queries resident, stream
// 32-key chunks of the 2112-token KV with online softmax.
// Q: [B*64, 1024] (head h at col h*64), KV: [B*2112, 2048] (K|V)
// O: [B*64, 1024]
// ---------------------------------------------------------------------------
__global__ __launch_bounds__(256) void attn_kernel(
    const float* __restrict__ Q, const float* __restrict__ KV, float* __restrict__ O)
{
    const int bh = blockIdx.x;
    const int b  = bh >> 4;
    const int h  = bh & 15;

    __shared__ float qs[64][64];
    __shared__ float ks[32][65];
    __shared__ float vs[32][65];
    __shared__ float Ss[64][33];

    const int tid = threadIdx.x;
    const int r  = tid >> 2;         // query row 0..63
    const int g  = tid & 3;          // sub-lane in 4-group
    const int j0 = g << 3;           // key offset for score phase
    const int d0 = g << 4;           // dim offset for accum phase

    // load q, fold in full softmax scale (64^-0.25)^2 = 0.125
    const float* Qb = Q + ((size_t)b * 64) * 1024 + h * 64;
    for (int i = tid; i < 64 * 64; i += 256) {
        int qr = i >> 6, qd = i & 63;
        qs[qr][qd] = Qb[(size_t)qr * 1024 + qd] * 0.125f;
    }

    float m_r = -1e30f, l_r = 0.f;
    float oacc[16];
    #pragma unroll
    for (int i = 0; i < 16; i++) oacc[i] = 0.f;

    const float* KVb = KV + ((size_t)b * 2112) * 2048;

    for (int c = 0; c < 66; c++) {          // 66 * 32 = 2112
        const int n0 = c << 5;
        __syncthreads();
        for (int i = tid; i < 32 * 64; i += 256) {
            int kr = i >> 6, kd = i & 63;
            const float* row = KVb + (size_t)(n0 + kr) * 2048 + h * 64;
            ks[kr][kd] = row[kd];
            vs[kr][kd] = row[1024 + kd];
        }
        __syncthreads();

        // scores for (row r, keys j0..j0+7)
        float sv[8];
        #pragma unroll
        for (int jj = 0; jj < 8; jj++) {
            float s = 0.f;
            #pragma unroll
            for (int d = 0; d < 64; d++) s += qs[r][d] * ks[j0 + jj][d];
            sv[jj] = s;
        }
        float cm = sv[0];
        #pragma unroll
        for (int jj = 1; jj < 8; jj++) cm = fmaxf(cm, sv[jj]);
        cm = fmaxf(cm, __shfl_xor_sync(0xffffffffu, cm, 1));
        cm = fmaxf(cm, __shfl_xor_sync(0xffffffffu, cm, 2));

        float mnew  = fmaxf(m_r, cm);
        float alpha = __expf(m_r - mnew);
        float ps = 0.f;
        #pragma unroll
        for (int jj = 0; jj < 8; jj++) {
            float p = __expf(sv[jj] - mnew);
            Ss[r][j0 + jj] = p;
            ps += p;
        }
        ps += __shfl_xor_sync(0xffffffffu, ps, 1);
        ps += __shfl_xor_sync(0xffffffffu, ps, 2);
        l_r = l_r * alpha + ps;
        m_r = mnew;
        __syncwarp();

        #pragma unroll
        for (int di = 0; di < 16; di++) oacc[di] *= alpha;
        #pragma unroll 4
        for (int j = 0; j < 32; j++) {
            float p = Ss[r][j];
            #pragma unroll
            for (int di = 0; di < 16; di++)
                oacc[di] += p * vs[j][d0 + di];
        }
        __syncwarp();
    }

    float inv = 1.0f / l_r;
    float* Ob = O + ((size_t)(b * 64 + r)) * 1024 + h * 64 + d0;
    #pragma unroll
    for (int di = 0; di < 16; di++) Ob[di] = oacc[di] * inv;
}

// ---------------------------------------------------------------------------
// Launch
// ---------------------------------------------------------------------------
extern "C" void kernel_launch(void* const* d_in, const int* in_sizes, int n_in,
                              void* d_out, int out_size)
{
    const float* x       = (const float*)d_in[0];
    const float* latents = (const float*)d_in[1];
    const float* n1s     = (const float*)d_in[2];
    const float* n1b     = (const float*)d_in[3];
    const float* n2s     = (const float*)d_in[4];
    const float* n2b     = (const float*)d_in[5];
    const float* Wq      = (const float*)d_in[6];
    const float* Wkv     = (const float*)d_in[7];
    const float* Wo      = (const float*)d_in[8];
    const float* ffs     = (const float*)d_in[9];
    const float* ffb     = (const float*)d_in[10];
    const float* W1      = (const float*)d_in[11];
    const float* W2      = (const float*)d_in[12];
    const float* projw   = (const float*)d_in[13];
    const float* projb   = (const float*)d_in[14];
    const float* outs    = (const float*)d_in[15];
    const float* outb    = (const float*)d_in[16];
    float* out = (float*)d_out;

    float *xcat, *kv, *lat, *ltn, *q, *o, *hbuf, *t2;
    cudaGetSymbolAddress((void**)&xcat, g_xcat);
    cudaGetSymbolAddress((void**)&kv,   g_kv);
    cudaGetSymbolAddress((void**)&lat,  g_lat);
    cudaGetSymbolAddress((void**)&ltn,  g_ltn);
    cudaGetSymbolAddress((void**)&q,    g_q);
    cudaGetSymbolAddress((void**)&o,    g_o);
    cudaGetSymbolAddress((void**)&hbuf, g_h);
    cudaGetSymbolAddress((void**)&t2,   g_t2);

    // lat = broadcast(latents)
    bcast_kernel<<<8192, 256>>>(latents, lat);

    const dim3 gq (1024 / 128, 2048 / 128);    // (8, 16)    N=1024 GEMMs on 2048 rows
    const dim3 gkv(2048 / 128, 67584 / 128);   // (16, 528)  KV GEMM
    const dim3 g1 (4096 / 128, 2048 / 128);    // (32, 16)   FFN up

    for (int i = 0; i < 2; i++) {
        // xn = LN(x) -> xcat rows [b*2112 + 0, 2048)
        ln_kernel<<<65536, 256>>>(x, xcat, n1s + i * 1024, n1b + i * 1024, 2048, 2112, 0);
        // ltn = LN(lat) -> contiguous, and -> xcat rows [b*2112 + 2048, 2112)
        ln_kernel<<<2048, 256>>>(lat, ltn,  n2s + i * 1024, n2b + i * 1024, 2048, 2048, 0);
        ln_kernel<<<2048, 256>>>(lat, xcat, n2s + i * 1024, n2b + i * 1024, 64, 2112, 2048);

        // q = ltn @ Wq[i]
        sgemm_kernel<<<gq, 256>>>(ltn, Wq + (size_t)i * 1048576, nullptr, nullptr,
                                  q, 2048, 1024, 1024, 0);
        // kv = xcat @ Wkv[i]
        sgemm_kernel<<<gkv, 256>>>(xcat, Wkv + (size_t)i * 2097152, nullptr, nullptr,
                                   kv, 67584, 2048, 1024, 0);
        // attention
        attn_kernel<<<512, 256>>>(q, kv, o);
        // lat = lat + o @ Wo[i]
        sgemm_kernel<<<gq, 256>>>(o, Wo + (size_t)i * 1048576, lat, nullptr,
                                  lat, 2048, 1024, 1024, F_RES);
        // h = gelu(LN_ff(lat) @ W1[i])
        ln_kernel<<<2048, 256>>>(lat, ltn, ffs + i * 1024, ffb + i * 1024, 2048, 2048, 0);
        sgemm_kernel<<<g1, 256>>>(ltn, W1 + (size_t)i * 4194304, nullptr, nullptr,
                                  hbuf, 2048, 4096, 1024, F_GELU);
        // lat = lat + h @ W2[i]
        sgemm_kernel<<<gq, 256>>>(hbuf, W2 + (size_t)i * 4194304, lat, nullptr,
                                  lat, 2048, 1024, 4096, F_RES);
    }

    // out = LN(lat @ proj_w + proj_b)
    sgemm_kernel<<<gq, 256>>>(lat, projw, nullptr, projb, t2, 2048, 1024, 1024, F_BIAS);
    ln_kernel<<<2048, 256>>>(t2, out, outs, outb, 2048, 2048, 0);
}

// round 5
// speedup vs baseline: 2.8504x; 2.8467x over previous
#include <cuda_runtime.h>
#include <cstdint>
#include <math.h>

// B=32, N1=2048, DIM=1024, HEADS=16, DH=64, NQ=64, L=2, FF=4096
#define F_RES  1
#define F_GELU 4
#define F_RND  8

// ---- scratch (device globals; allocation-free rule) ----
__device__ float g_z   [67108864];   // 65536 x 1024  unit-LN(x), tf32-rounded
__device__ float g_kvX [134217728];  // 65536 x 2048
__device__ float g_kvL [4194304];    // 2048  x 2048
__device__ float g_lat [2097152];
__device__ float g_ltn [2097152];
__device__ float g_q   [2097152];
__device__ float g_o   [2097152];
__device__ float g_t2  [2097152];
__device__ float g_h   [8388608];    // 2048 x 4096
__device__ float g_WqR [2097152];    // 2 x (1024x1024)   tf32-rounded weights
__device__ float g_WoR [2097152];
__device__ float g_prR [1048576];
__device__ float g_WkvRs[4194304];   // 2 x (1024x2048) scaled by norm1_s, rounded
__device__ float g_WkvRp[4194304];   // 2 x (1024x2048) plain, rounded
__device__ float g_W1R [8388608];    // 2 x (1024x4096)
__device__ float g_W2R [8388608];    // 2 x (4096x1024)
__device__ float g_bkv [4096];       // 2 x 2048 folded norm1_b @ Wkv

// ---------------------------------------------------------------------------
__device__ __forceinline__ uint32_t s2u(const void* p) {
    return (uint32_t)__cvta_generic_to_shared(p);
}
__device__ __forceinline__ float rtf32(float x) {
    uint32_t u;
    asm("cvt.rn.tf32.f32 %0, %1;" : "=r"(u) : "f"(x));
    return __uint_as_float(u);
}
__device__ __forceinline__ void cpasync16(uint32_t dst, const float* src) {
    asm volatile("cp.async.cg.shared.global [%0], [%1], 16;" :: "r"(dst), "l"(src) : "memory");
}
__device__ __forceinline__ float gelu_f(float x) {
    float x3 = x * x * x;
    return 0.5f * x * (1.0f + tanhf(0.7978845608028654f * (x + 0.044715f * x3)));
}

// ---------------------------------------------------------------------------
// tf32 mma.sync GEMM: C[M,N] = A[M,K] @ B[K,N]  (+bias/gelu/residual/round)
// BM=128, BN=128, BK=32, 256 threads (8 warps, 2x4), warp tile 64x32,
// m16n8k8 fragments, 4-stage cp.async pipeline.
// M%128==0, N%128==0, K%32==0, K>=128. All operands pre-rounded to tf32.
// ---------------------------------------------------------------------------
#define AS_STRIDE 36                   // floats per A row
#define BS_STRIDE 136                  // floats per B row
#define A_TILE_F  (128 * AS_STRIDE)    // 4608 floats
#define B_TILE_F  (32 * BS_STRIDE)     // 4352 floats
#define STG_F     (A_TILE_F + B_TILE_F)
#define SMEM_TC   (4 * STG_F * 4)      // 143360 bytes

__device__ __forceinline__ void load_tile(
    float* sm, int s, const float* __restrict__ A, const float* __restrict__ Bw,
    int K, int N, size_t rowBase, size_t colBase, int t, int tid)
{
    float* As = sm + s * STG_F;
    float* Bs = As + A_TILE_F;
    const float* Ag = A + rowBase * K + t * 32;
    const float* Bg = Bw + (size_t)(t * 32) * N + colBase;
#pragma unroll
    for (int i = 0; i < 4; i++) {                  // A: 128 rows x 8 chunks
        int ch = tid + (i << 8);
        int r = ch >> 3, c = ch & 7;
        cpasync16(s2u(As + r * AS_STRIDE + c * 4), Ag + (size_t)r * K + c * 4);
    }
#pragma unroll
    for (int i = 0; i < 4; i++) {                  // B: 32 rows x 32 chunks
        int ch = tid + (i << 8);
        int r = ch >> 5, c = ch & 31;
        cpasync16(s2u(Bs + r * BS_STRIDE + c * 4), Bg + (size_t)r * N + c * 4);
    }
    asm volatile("cp.async.commit_group;" ::: "memory");
}

__global__ __launch_bounds__(256, 1) void tc_gemm(
    const float* __restrict__ A, const float* __restrict__ Bw,
    const float* __restrict__ Cin, const float* __restrict__ bias,
    float* __restrict__ C, int M, int N, int K, int flags)
{
    extern __shared__ __align__(16) float sm[];
    const int tid = threadIdx.x, wid = tid >> 5, lane = tid & 31;
    const int wm = wid & 1, wn = wid >> 1;         // 2x4 warp grid
    const int gid = lane >> 2, tg = lane & 3;
    const size_t rowBase = (size_t)blockIdx.y * 128;
    const size_t colBase = (size_t)blockIdx.x * 128;

    float c[4][4][4];
#pragma unroll
    for (int mi = 0; mi < 4; mi++)
#pragma unroll
        for (int ni = 0; ni < 4; ni++)
#pragma unroll
            for (int k = 0; k < 4; k++) c[mi][ni][k] = 0.f;

    const int KT = K >> 5;
#pragma unroll
    for (int t = 0; t < 3; t++) load_tile(sm, t, A, Bw, K, N, rowBase, colBase, t, tid);

    for (int t = 0; t < KT; t++) {
        const int s = t & 3;
        asm volatile("cp.async.wait_group 2;" ::: "memory");
        __syncthreads();
        const int tp = t + 3;
        if (tp < KT) load_tile(sm, tp & 3, A, Bw, K, N, rowBase, colBase, tp, tid);

        const float* As = sm + s * STG_F;
        const float* Bs = As + A_TILE_F;
#pragma unroll
        for (int kb = 0; kb < 4; kb++) {
            const int k0 = kb << 3;
            uint32_t a[4][4], b[4][2];
#pragma unroll
            for (int mi = 0; mi < 4; mi++) {
                const float* ap = As + (wm * 64 + mi * 16 + gid) * AS_STRIDE + k0 + tg;
                a[mi][0] = __float_as_uint(ap[0]);
                a[mi][1] = __float_as_uint(ap[8 * AS_STRIDE]);
                a[mi][2] = __float_as_uint(ap[4]);
                a[mi][3] = __float_as_uint(ap[8 * AS_STRIDE + 4]);
            }
#pragma unroll
            for (int ni = 0; ni < 4; ni++) {
                const float* bp = Bs + (k0 + tg) * BS_STRIDE + wn * 32 + ni * 8 + gid;
                b[ni][0] = __float_as_uint(bp[0]);
                b[ni][1] = __float_as_uint(bp[4 * BS_STRIDE]);
            }
#pragma unroll
            for (int mi = 0; mi < 4; mi++)
#pragma unroll
                for (int ni = 0; ni < 4; ni++) {
                    asm volatile(
                        "mma.sync.aligned.m16n8k8.row.col.f32.tf32.tf32.f32 "
                        "{%0,%1,%2,%3}, {%4,%5,%6,%7}, {%8,%9}, {%0,%1,%2,%3};"
                        : "+f"(c[mi][ni][0]), "+f"(c[mi][ni][1]),
                          "+f"(c[mi][ni][2]), "+f"(c[mi][ni][3])
                        : "r"(a[mi][0]), "r"(a[mi][1]), "r"(a[mi][2]), "r"(a[mi][3]),
                          "r"(b[ni][0]), "r"(b[ni][1]));
                }
        }
    }

    // epilogue
#pragma unroll
    for (int mi = 0; mi < 4; mi++) {
        const size_t r0 = rowBase + wm * 64 + mi * 16 + gid;
        const size_t r1 = r0 + 8;
#pragma unroll
        for (int ni = 0; ni < 4; ni++) {
            const size_t col = colBase + wn * 32 + ni * 8 + tg * 2;
            float v0 = c[mi][ni][0], v1 = c[mi][ni][1];
            float v2 = c[mi][ni][2], v3 = c[mi][ni][3];
            if (bias) {
                float b0 = bias[col], b1 = bias[col + 1];
                v0 += b0; v1 += b1; v2 += b0; v3 += b1;
            }
            if (flags & F_GELU) {
                v0 = gelu_f(v0); v1 = gelu_f(v1); v2 = gelu_f(v2); v3 = gelu_f(v3);
            }
            if (flags & F_RES) {
                const float2 p0 = *(const float2*)(Cin + r0 * N + col);
                const float2 p1 = *(const float2*)(Cin + r1 * N + col);
                v0 += p0.x; v1 += p0.y; v2 += p1.x; v3 += p1.y;
            }
            if (flags & F_RND) {
                v0 = rtf32(v0); v1 = rtf32(v1); v2 = rtf32(v2); v3 = rtf32(v3);
            }
            *(float2*)(C + r0 * N + col) = make_float2(v0, v1);
            *(float2*)(C + r1 * N + col) = make_float2(v2, v3);
        }
    }
}

// ---------------------------------------------------------------------------
__global__ void bcast_kernel(const float* __restrict__ lat0, float* __restrict__ lat)
{
    int i = blockIdx.x * 256 + threadIdx.x;
    lat[i] = lat0[i & 65535];
}

// ---------------------------------------------------------------------------
// LayerNorm over 1024 cols, single pass. gs==null -> unit affine. rnd -> tf32.
// ---------------------------------------------------------------------------
__global__ __launch_bounds__(256) void ln_kernel(
    const float* __restrict__ in, float* __restrict__ out,
    const float* __restrict__ gs, const float* __restrict__ gb, int rnd)
{
    __shared__ float r1[8], r2[8], bc[2];
    int r = blockIdx.x, tid = threadIdx.x;
    const float4 xv = ((const float4*)(in + (size_t)r * 1024))[tid];

    float s  = xv.x + xv.y + xv.z + xv.w;
    float s2 = xv.x*xv.x + xv.y*xv.y + xv.z*xv.z + xv.w*xv.w;
#pragma unroll
    for (int o = 16; o; o >>= 1) {
        s  += __shfl_xor_sync(0xffffffffu, s,  o);
        s2 += __shfl_xor_sync(0xffffffffu, s2, o);
    }
    if ((tid & 31) == 0) { r1[tid >> 5] = s; r2[tid >> 5] = s2; }
    __syncthreads();
    if (tid == 0) {
        float t1 = 0.f, t2 = 0.f;
#pragma unroll
        for (int i = 0; i < 8; i++) { t1 += r1[i]; t2 += r2[i]; }
        float m = t1 * (1.0f / 1024.0f);
        bc[0] = m;
        bc[1] = rsqrtf(t2 * (1.0f / 1024.0f) - m * m + 1e-5f);
    }
    __syncthreads();
    float mean = bc[0], inv = bc[1];

    float4 ov;
    ov.x = (xv.x - mean) * inv; ov.y = (xv.y - mean) * inv;
    ov.z = (xv.z - mean) * inv; ov.w = (xv.w - mean) * inv;
    if (gs) {
        const float4 sv = ((const float4*)gs)[tid];
        const float4 bv = ((const float4*)gb)[tid];
        ov.x = ov.x * sv.x + bv.x; ov.y = ov.y * sv.y + bv.y;
        ov.z = ov.z * sv.z + bv.z; ov.w = ov.w * sv.w + bv.w;
    }
    if (rnd) { ov.x = rtf32(ov.x); ov.y = rtf32(ov.y); ov.z = rtf32(ov.z); ov.w = rtf32(ov.w); }
    ((float4*)(out + (size_t)r * 1024))[tid] = ov;
}

// ---------------------------------------------------------------------------
// weight prep: out[i] = rtf32(in[i] * (sc ? sc[i/N] : 1))
// ---------------------------------------------------------------------------
__global__ void wprep_kernel(const float* __restrict__ in, float* __restrict__ out,
                             int total, const float* __restrict__ sc, int N)
{
    int i = blockIdx.x * 256 + threadIdx.x;
    if (i < total) {
        float v = in[i];
        if (sc) v *= sc[i / N];
        out[i] = rtf32(v);
    }
}

// ---------------------------------------------------------------------------
// bias fold: bias[j] = sum_k b[k] * W[k,j]   (W: [1024, N])
// ---------------------------------------------------------------------------
__global__ void gemv_bias_kernel(const float* __restrict__ b, const float* __restrict__ W,
                                 float* __restrict__ bias, int N)
{
    int j = blockIdx.x * 256 + threadIdx.x;
    float s = 0.f;
    for (int k = 0; k < 1024; k++) s += b[k] * W[(size_t)k * N + j];
    bias[j] = s;
}

// ---------------------------------------------------------------------------
// Attention: block = (b,h). 64 queries resident, 64-key chunks, online softmax.
// Keys 0..2047 from kvX (rows b*2048+n), keys 2048..2111 from kvL (rows b*64+..).
// ---------------------------------------------------------------------------
#define SMEM_ATT (4 * 64 * 68 * 4)

__global__ __launch_bounds__(256) void attn_kernel(
    const float* __restrict__ Q, const float* __restrict__ KX,
    const float* __restrict__ KL, float* __restrict__ O)
{
    extern __shared__ __align__(16) float smA[];
    float* qs = smA;                 // [64][68]
    float* ks = smA + 64 * 68;
    float* vs = smA + 2 * 64 * 68;
    float* Ss = smA + 3 * 64 * 68;

    const int bh = blockIdx.x, b = bh >> 4, h = bh & 15;
    const int tid = threadIdx.x;
    const int ty = tid >> 4, tx = tid & 15;
    const int Q0 = ty << 2, X0 = tx << 2;

    const float* Qb = Q + ((size_t)b * 64) * 1024 + h * 64;
#pragma unroll
    for (int rep = 0; rep < 4; rep++) {
        int id = tid + (rep << 8);
        int r = id >> 4, cc = (id & 15) << 2;
        float4 v = *(const float4*)(Qb + (size_t)r * 1024 + cc);
        v.x *= 0.125f; v.y *= 0.125f; v.z *= 0.125f; v.w *= 0.125f;
        *(float4*)(qs + r * 68 + cc) = v;
    }

    float m[4], l[4], oacc[4][4];
#pragma unroll
    for (int i = 0; i < 4; i++) {
        m[i] = -1e30f; l[i] = 0.f;
#pragma unroll
        for (int j = 0; j < 4; j++) oacc[i][j] = 0.f;
    }

    for (int c = 0; c < 33; c++) {
        __syncthreads();
        const float* base = (c < 32)
            ? KX + ((size_t)(b * 2048 + c * 64)) * 2048 + h * 64
            : KL + ((size_t)(b * 64)) * 2048 + h * 64;
#pragma unroll
        for (int rep = 0; rep < 4; rep++) {
            int id = tid + (rep << 8);
            int r = id >> 4, cc = (id & 15) << 2;
            *(float4*)(ks + r * 68 + cc) = *(const float4*)(base + (size_t)r * 2048 + cc);
            *(float4*)(vs + r * 68 + cc) = *(const float4*)(base + (size_t)r * 2048 + 1024 + cc);
        }
        __syncthreads();

        float s[4][4];
#pragma unroll
        for (int i = 0; i < 4; i++)
#pragma unroll
            for (int j = 0; j < 4; j++) s[i][j] = 0.f;
        for (int d = 0; d < 64; d += 4) {
            float4 qv[4], kv4[4];
#pragma unroll
            for (int i = 0; i < 4; i++) qv[i]  = *(const float4*)(qs + (Q0 + i) * 68 + d);
#pragma unroll
            for (int j = 0; j < 4; j++) kv4[j] = *(const float4*)(ks + (X0 + j) * 68 + d);
#pragma unroll
            for (int i = 0; i < 4; i++)
#pragma unroll
                for (int j = 0; j < 4; j++)
                    s[i][j] += qv[i].x * kv4[j].x + qv[i].y * kv4[j].y
                             + qv[i].z * kv4[j].z + qv[i].w * kv4[j].w;
        }
#pragma unroll
        for (int i = 0; i < 4; i++) {
            float mx = fmaxf(fmaxf(s[i][0], s[i][1]), fmaxf(s[i][2], s[i][3]));
#pragma unroll
            for (int o = 1; o < 16; o <<= 1) mx = fmaxf(mx, __shfl_xor_sync(0xffffffffu, mx, o));
            float mn = fmaxf(m[i], mx);
            float al = __expf(m[i] - mn);
            float ps = 0.f;
#pragma unroll
            for (int j = 0; j < 4; j++) {
                float p = __expf(s[i][j] - mn);
                Ss[(Q0 + i) * 68 + X0 + j] = p;
                ps += p;
            }
#pragma unroll
            for (int o = 1; o < 16; o <<= 1) ps += __shfl_xor_sync(0xffffffffu, ps, o);
            l[i] = l[i] * al + ps;
            m[i] = mn;
#pragma unroll
            for (int j = 0; j < 4; j++) oacc[i][j] *= al;
        }
        __syncthreads();

        for (int j = 0; j < 64; j += 4) {
            float4 vv[4], pv[4];
#pragma unroll
            for (int jj = 0; jj < 4; jj++) vv[jj] = *(const float4*)(vs + (j + jj) * 68 + X0);
#pragma unroll
            for (int i = 0; i < 4; i++)  pv[i] = *(const float4*)(Ss + (Q0 + i) * 68 + j);
#pragma unroll
            for (int i = 0; i < 4; i++) {
                oacc[i][0] += pv[i].x * vv[0].x + pv[i].y * vv[1].x + pv[i].z * vv[2].x + pv[i].w * vv[3].x;
                oacc[i][1] += pv[i].x * vv[0].y + pv[i].y * vv[1].y + pv[i].z * vv[2].y + pv[i].w * vv[3].y;
                oacc[i][2] += pv[i].x * vv[0].z + pv[i].y * vv[1].z + pv[i].z * vv[2].z + pv[i].w * vv[3].z;
                oacc[i][3] += pv[i].x * vv[0].w + pv[i].y * vv[1].w + pv[i].z * vv[2].w + pv[i].w * vv[3].w;
            }
        }
    }

#pragma unroll
    for (int i = 0; i < 4; i++) {
        float inv = 1.0f / l[i];
        float* Ob = O + ((size_t)(b * 64 + Q0 + i)) * 1024 + h * 64 + X0;
        Ob[0] = rtf32(oacc[i][0] * inv);
        Ob[1] = rtf32(oacc[i][1] * inv);
        Ob[2] = rtf32(oacc[i][2] * inv);
        Ob[3] = rtf32(oacc[i][3] * inv);
    }
}

// ---------------------------------------------------------------------------
// Launch
// ---------------------------------------------------------------------------
extern "C" void kernel_launch(void* const* d_in, const int* in_sizes, int n_in,
                              void* d_out, int out_size)
{
    const float* x       = (const float*)d_in[0];
    const float* latents = (const float*)d_in[1];
    const float* n1s     = (const float*)d_in[2];
    const float* n1b     = (const float*)d_in[3];
    const float* n2s     = (const float*)d_in[4];
    const float* n2b     = (const float*)d_in[5];
    const float* Wq      = (const float*)d_in[6];
    const float* Wkv     = (const float*)d_in[7];
    const float* Wo      = (const float*)d_in[8];
    const float* ffs     = (const float*)d_in[9];
    const float* ffb     = (const float*)d_in[10];
    const float* W1      = (const float*)d_in[11];
    const float* W2      = (const float*)d_in[12];
    const float* projw   = (const float*)d_in[13];
    const float* projb   = (const float*)d_in[14];
    const float* outs    = (const float*)d_in[15];
    const float* outb    = (const float*)d_in[16];
    float* out = (float*)d_out;

    float *z, *kvX, *kvL, *lat, *ltn, *q, *o, *t2, *hbuf;
    float *WqR, *WoR, *prR, *WkvRs, *WkvRp, *W1R, *W2R, *bkv;
    cudaGetSymbolAddress((void**)&z,    g_z);
    cudaGetSymbolAddress((void**)&kvX,  g_kvX);
    cudaGetSymbolAddress((void**)&kvL,  g_kvL);
    cudaGetSymbolAddress((void**)&lat,  g_lat);
    cudaGetSymbolAddress((void**)&ltn,  g_ltn);
    cudaGetSymbolAddress((void**)&q,    g_q);
    cudaGetSymbolAddress((void**)&o,    g_o);
    cudaGetSymbolAddress((void**)&t2,   g_t2);
    cudaGetSymbolAddress((void**)&hbuf, g_h);
    cudaGetSymbolAddress((void**)&WqR,  g_WqR);
    cudaGetSymbolAddress((void**)&WoR,  g_WoR);
    cudaGetSymbolAddress((void**)&prR,  g_prR);
    cudaGetSymbolAddress((void**)&WkvRs,g_WkvRs);
    cudaGetSymbolAddress((void**)&WkvRp,g_WkvRp);
    cudaGetSymbolAddress((void**)&W1R,  g_W1R);
    cudaGetSymbolAddress((void**)&W2R,  g_W2R);
    cudaGetSymbolAddress((void**)&bkv,  g_bkv);

    cudaFuncSetAttribute(tc_gemm, cudaFuncAttributeMaxDynamicSharedMemorySize, SMEM_TC);
    cudaFuncSetAttribute(attn_kernel, cudaFuncAttributeMaxDynamicSharedMemorySize, SMEM_ATT);

    // ---- one-time prep ----
    bcast_kernel<<<8192, 256>>>(latents, lat);
    ln_kernel<<<65536, 256>>>(x, z, nullptr, nullptr, 1);   // unit-LN(x), rounded

    for (int i = 0; i < 2; i++) {
        wprep_kernel<<<4096, 256>>>(Wq  + (size_t)i*1048576, WqR  + (size_t)i*1048576, 1048576, nullptr, 0);
        wprep_kernel<<<8192, 256>>>(Wkv + (size_t)i*2097152, WkvRs+ (size_t)i*2097152, 2097152, n1s + i*1024, 2048);
        wprep_kernel<<<8192, 256>>>(Wkv + (size_t)i*2097152, WkvRp+ (size_t)i*2097152, 2097152, nullptr, 0);
        wprep_kernel<<<4096, 256>>>(Wo  + (size_t)i*1048576, WoR  + (size_t)i*1048576, 1048576, nullptr, 0);
        wprep_kernel<<<16384,256>>>(W1  + (size_t)i*4194304, W1R  + (size_t)i*4194304, 4194304, nullptr, 0);
        wprep_kernel<<<16384,256>>>(W2  + (size_t)i*4194304, W2R  + (size_t)i*4194304, 4194304, nullptr, 0);
        gemv_bias_kernel<<<8, 256>>>(n1b + i*1024, Wkv + (size_t)i*2097152, bkv + i*2048, 2048);
    }
    wprep_kernel<<<4096, 256>>>(projw, prR, 1048576, nullptr, 0);

    // ---- layers ----
    for (int i = 0; i < 2; i++) {
        ln_kernel<<<2048, 256>>>(lat, ltn, n2s + i*1024, n2b + i*1024, 1);

        // q = ltn @ Wq
        tc_gemm<<<dim3(8, 16), 256, SMEM_TC>>>(ltn, WqR + (size_t)i*1048576,
            nullptr, nullptr, q, 2048, 1024, 1024, 0);
        // kvX = z @ (s1*Wkv) + b1@Wkv
        tc_gemm<<<dim3(16, 512), 256, SMEM_TC>>>(z, WkvRs + (size_t)i*2097152,
            nullptr, bkv + i*2048, kvX, 65536, 2048, 1024, 0);
        // kvL = ltn @ Wkv
        tc_gemm<<<dim3(16, 16), 256, SMEM_TC>>>(ltn, WkvRp + (size_t)i*2097152,
            nullptr, nullptr, kvL, 2048, 2048, 1024, 0);

        attn_kernel<<<512, 256, SMEM_ATT>>>(q, kvX, kvL, o);

        // lat += o @ Wo
        tc_gemm<<<dim3(8, 16), 256, SMEM_TC>>>(o, WoR + (size_t)i*1048576,
            lat, nullptr, lat, 2048, 1024, 1024, F_RES);
        // h = gelu(LN_ff(lat) @ W1), rounded
        ln_kernel<<<2048, 256>>>(lat, ltn, ffs + i*1024, ffb + i*1024, 1);
        tc_gemm<<<dim3(32, 16), 256, SMEM_TC>>>(ltn, W1R + (size_t)i*4194304,
            nullptr, nullptr, hbuf, 2048, 4096, 1024, F_GELU | F_RND);
        // lat += h @ W2   (round after layer 2: lat then feeds proj GEMM as A)
        tc_gemm<<<dim3(8, 16), 256, SMEM_TC>>>(hbuf, W2R + (size_t)i*4194304,
            lat, nullptr, lat, 2048, 1024, 4096, F_RES | (i == 1 ? F_RND : 0));
    }

    // out = LN(lat @ proj_w + proj_b)
    tc_gemm<<<dim3(8, 16), 256, SMEM_TC>>>(lat, prR, nullptr, projb, t2, 2048, 1024, 1024, 0);
    ln_kernel<<<2048, 256>>>(t2, out, outs, outb, 0);
}

// round 6
// speedup vs baseline: 3.8581x; 1.3535x over previous
#include <cuda_runtime.h>
#include <cuda_fp16.h>
#include <cstdint>
#include <math.h>

// B=32, N1=2048, DIM=1024, HEADS=16, DH=64, NQ=64, L=2, FF=4096
#define F_RES  1
#define F_GELU 4
#define F_HALF 8

// ---- scratch (device globals; allocation-free rule) ----
__device__ __half g_z   [67108864];   // 65536 x 1024  unit-LN(x)
__device__ __half g_kvX [134217728];  // 65536 x 2048
__device__ __half g_kvL [4194304];    // 2048  x 2048
__device__ float  g_lat [2097152];
__device__ __half g_latH[2097152];
__device__ __half g_ltn [2097152];
__device__ __half g_q   [2097152];
__device__ __half g_o   [2097152];
__device__ float  g_t2  [2097152];
__device__ __half g_h   [8388608];    // 2048 x 4096
__device__ __half g_WqT [2097152];    // 2 x [1024][1024]  (transposed [N][K])
__device__ __half g_WoT [2097152];
__device__ __half g_prT [1048576];
__device__ __half g_WkvTs[4194304];   // 2 x [2048][1024] scaled by norm1_s
__device__ __half g_WkvTp[4194304];   // 2 x [2048][1024]
__device__ __half g_W1T [8388608];    // 2 x [4096][1024]
__device__ __half g_W2T [8388608];    // 2 x [1024][4096]
__device__ float  g_bkv [4096];       // 2 x 2048 folded norm1_b @ Wkv

// ---------------------------------------------------------------------------
__device__ __forceinline__ uint32_t s2u(const void* p) {
    return (uint32_t)__cvta_generic_to_shared(p);
}
__device__ __forceinline__ void cpasync16(uint32_t dst, const void* src) {
    asm volatile("cp.async.cg.shared.global [%0], [%1], 16;" :: "r"(dst), "l"(src) : "memory");
}
__device__ __forceinline__ float gelu_f(float x) {
    float x3 = x * x * x;
    return 0.5f * x * (1.0f + tanhf(0.7978845608028654f * (x + 0.044715f * x3)));
}

// ---------------------------------------------------------------------------
// fp16 mma GEMM: C[M,N] = A[M,K] @ Bt[N,K]^T  (+bias/gelu/residual)
// A: [M][K] half row-major. Bt: [N][K] half row-major (= "col" operand).
// BM=128, BN=128, BK=32, 8 warps (2x4), warp tile 64x32, m16n8k16,
// 4-stage cp.async pipeline. M%128==0, N%128==0, K%32==0, K>=128.
// Output: float* C (or half* Ch when F_HALF).
// ---------------------------------------------------------------------------
#define AS_H      40                   // halves per smem row (80B stride)
#define TILE_H    (128 * AS_H)         // 5120 halves per operand tile
#define STG_H     (2 * TILE_H)         // A tile + B tile
#define SMEM_TC   (4 * STG_H * 2)      // 81920 bytes

__device__ __forceinline__ void load_tile(
    __half* sm, int s, const __half* __restrict__ A, const __half* __restrict__ Bt,
    int K, size_t rowBase, size_t colBase, int t, int tid)
{
    __half* As = sm + s * STG_H;
    __half* Bs = As + TILE_H;
    const __half* Ag = A  + rowBase * K + t * 32;
    const __half* Bg = Bt + colBase * K + t * 32;
#pragma unroll
    for (int i = 0; i < 2; i++) {                  // A: 128 rows x 4 chunks(16B)
        int ch = tid + (i << 8);
        int r = ch >> 2, c = ch & 3;
        cpasync16(s2u(As + r * AS_H + c * 8), Ag + (size_t)r * K + c * 8);
    }
#pragma unroll
    for (int i = 0; i < 2; i++) {                  // B: 128 rows x 4 chunks
        int ch = tid + (i << 8);
        int r = ch >> 2, c = ch & 3;
        cpasync16(s2u(Bs + r * AS_H + c * 8), Bg + (size_t)r * K + c * 8);
    }
    asm volatile("cp.async.commit_group;" ::: "memory");
}

__global__ __launch_bounds__(256, 1) void tc_gemm(
    const __half* __restrict__ A, const __half* __restrict__ Bt,
    const float* __restrict__ Cin, const float* __restrict__ bias,
    float* __restrict__ C, __half* __restrict__ Ch,
    int M, int N, int K, int flags)
{
    extern __shared__ __align__(16) __half sm[];
    const int tid = threadIdx.x, wid = tid >> 5, lane = tid & 31;
    const int wm = wid & 1, wn = wid >> 1;         // 2x4 warp grid
    const int gid = lane >> 2, tg = lane & 3;
    const size_t rowBase = (size_t)blockIdx.y * 128;
    const size_t colBase = (size_t)blockIdx.x * 128;

    float c[4][4][4];
#pragma unroll
    for (int mi = 0; mi < 4; mi++)
#pragma unroll
        for (int ni = 0; ni < 4; ni++)
#pragma unroll
            for (int k = 0; k < 4; k++) c[mi][ni][k] = 0.f;

    const int KT = K >> 5;
#pragma unroll
    for (int t = 0; t < 3; t++) load_tile(sm, t, A, Bt, K, rowBase, colBase, t, tid);

    for (int t = 0; t < KT; t++) {
        const int s = t & 3;
        asm volatile("cp.async.wait_group 2;" ::: "memory");
        __syncthreads();
        const int tp = t + 3;
        if (tp < KT) load_tile(sm, tp & 3, A, Bt, K, rowBase, colBase, tp, tid);

        const __half* As = sm + s * STG_H;
        const __half* Bs = As + TILE_H;
#pragma unroll
        for (int ks = 0; ks < 2; ks++) {
            const int k0 = ks << 4;
            uint32_t a[4][4], b[4][2];
#pragma unroll
            for (int mi = 0; mi < 4; mi++) {
                const __half* ap = As + (wm * 64 + mi * 16 + gid) * AS_H + k0 + 2 * tg;
                a[mi][0] = *(const uint32_t*)(ap);
                a[mi][1] = *(const uint32_t*)(ap + 8 * AS_H);
                a[mi][2] = *(const uint32_t*)(ap + 8);
                a[mi][3] = *(const uint32_t*)(ap + 8 * AS_H + 8);
            }
#pragma unroll
            for (int ni = 0; ni < 4; ni++) {
                const __half* bp = Bs + (wn * 32 + ni * 8 + gid) * AS_H + k0 + 2 * tg;
                b[ni][0] = *(const uint32_t*)(bp);
                b[ni][1] = *(const uint32_t*)(bp + 8);
            }
#pragma unroll
            for (int mi = 0; mi < 4; mi++)
#pragma unroll
                for (int ni = 0; ni < 4; ni++) {
                    asm volatile(
                        "mma.sync.aligned.m16n8k16.row.col.f32.f16.f16.f32 "
                        "{%0,%1,%2,%3}, {%4,%5,%6,%7}, {%8,%9}, {%0,%1,%2,%3};"
                        : "+f"(c[mi][ni][0]), "+f"(c[mi][ni][1]),
                          "+f"(c[mi][ni][2]), "+f"(c[mi][ni][3])
                        : "r"(a[mi][0]), "r"(a[mi][1]), "r"(a[mi][2]), "r"(a[mi][3]),
                          "r"(b[ni][0]), "r"(b[ni][1]));
                }
        }
    }

    // epilogue
#pragma unroll
    for (int mi = 0; mi < 4; mi++) {
        const size_t r0 = rowBase + wm * 64 + mi * 16 + gid;
        const size_t r1 = r0 + 8;
#pragma unroll
        for (int ni = 0; ni < 4; ni++) {
            const size_t col = colBase + wn * 32 + ni * 8 + tg * 2;
            float v0 = c[mi][ni][0], v1 = c[mi][ni][1];
            float v2 = c[mi][ni][2], v3 = c[mi][ni][3];
            if (bias) {
                float b0 = bias[col], b1 = bias[col + 1];
                v0 += b0; v1 += b1; v2 += b0; v3 += b1;
            }
            if (flags & F_GELU) {
                v0 = gelu_f(v0); v1 = gelu_f(v1); v2 = gelu_f(v2); v3 = gelu_f(v3);
            }
            if (flags & F_RES) {
                const float2 p0 = *(const float2*)(Cin + r0 * N + col);
                const float2 p1 = *(const float2*)(Cin + r1 * N + col);
                v0 += p0.x; v1 += p0.y; v2 += p1.x; v3 += p1.y;
            }
            if (flags & F_HALF) {
                *(__half2*)(Ch + r0 * N + col) = __floats2half2_rn(v0, v1);
                *(__half2*)(Ch + r1 * N + col) = __floats2half2_rn(v2, v3);
            } else {
                *(float2*)(C + r0 * N + col) = make_float2(v0, v1);
                *(float2*)(C + r1 * N + col) = make_float2(v2, v3);
            }
        }
    }
}

// ---------------------------------------------------------------------------
__global__ void bcast_kernel(const float* __restrict__ lat0, float* __restrict__ lat)
{
    int i = blockIdx.x * 256 + threadIdx.x;
    lat[i] = lat0[i & 65535];
}

__global__ void f2h_kernel(const float* __restrict__ in, __half* __restrict__ out)
{
    int i = blockIdx.x * 256 + threadIdx.x;
    out[i] = __float2half(in[i]);
}

// ---------------------------------------------------------------------------
// LayerNorm over 1024 cols, single pass. gs==null -> unit affine.
// Writes float (outF) or half (outH); exactly one non-null.
// ---------------------------------------------------------------------------
__global__ __launch_bounds__(256) void ln_kernel(
    const float* __restrict__ in, float* __restrict__ outF, __half* __restrict__ outH,
    const float* __restrict__ gs, const float* __restrict__ gb)
{
    __shared__ float r1[8], r2[8], bc[2];
    int r = blockIdx.x, tid = threadIdx.x;
    const float4 xv = ((const float4*)(in + (size_t)r * 1024))[tid];

    float s  = xv.x + xv.y + xv.z + xv.w;
    float s2 = xv.x*xv.x + xv.y*xv.y + xv.z*xv.z + xv.w*xv.w;
#pragma unroll
    for (int o = 16; o; o >>= 1) {
        s  += __shfl_xor_sync(0xffffffffu, s,  o);
        s2 += __shfl_xor_sync(0xffffffffu, s2, o);
    }
    if ((tid & 31) == 0) { r1[tid >> 5] = s; r2[tid >> 5] = s2; }
    __syncthreads();
    if (tid == 0) {
        float t1 = 0.f, t2 = 0.f;
#pragma unroll
        for (int i = 0; i < 8; i++) { t1 += r1[i]; t2 += r2[i]; }
        float m = t1 * (1.0f / 1024.0f);
        bc[0] = m;
        bc[1] = rsqrtf(t2 * (1.0f / 1024.0f) - m * m + 1e-5f);
    }
    __syncthreads();
    float mean = bc[0], inv = bc[1];

    float4 ov;
    ov.x = (xv.x - mean) * inv; ov.y = (xv.y - mean) * inv;
    ov.z = (xv.z - mean) * inv; ov.w = (xv.w - mean) * inv;
    if (gs) {
        const float4 sv = ((const float4*)gs)[tid];
        const float4 bv = ((const float4*)gb)[tid];
        ov.x = ov.x * sv.x + bv.x; ov.y = ov.y * sv.y + bv.y;
        ov.z = ov.z * sv.z + bv.z; ov.w = ov.w * sv.w + bv.w;
    }
    if (outH) {
        __half2* oh = (__half2*)(outH + (size_t)r * 1024);
        oh[tid * 2]     = __floats2half2_rn(ov.x, ov.y);
        oh[tid * 2 + 1] = __floats2half2_rn(ov.z, ov.w);
    } else {
        ((float4*)(outF + (size_t)r * 1024))[tid] = ov;
    }
}

// ---------------------------------------------------------------------------
// transpose: in[K][N] fp32 -> out[N][K] half, optional per-k scale
// grid (N/32, K/32), block (32, 8)
// ---------------------------------------------------------------------------
__global__ void transpose_kernel(const float* __restrict__ in, __half* __restrict__ out,
                                 int K, int N, const float* __restrict__ sc)
{
    __shared__ float t[32][33];
    int nb = blockIdx.x * 32, kb = blockIdx.y * 32;
    int tx = threadIdx.x, ty = threadIdx.y;
#pragma unroll
    for (int i = 0; i < 4; i++) {
        int k = kb + ty + i * 8;
        float v = in[(size_t)k * N + nb + tx];
        if (sc) v *= sc[k];
        t[ty + i * 8][tx] = v;
    }
    __syncthreads();
#pragma unroll
    for (int i = 0; i < 4; i++)
        out[(size_t)(nb + ty + i * 8) * K + kb + tx] = __float2half(t[tx][ty + i * 8]);
}

// ---------------------------------------------------------------------------
// bias fold: bias[j] = sum_k b[k] * W[k,j]   (W: [1024, N] fp32)
// ---------------------------------------------------------------------------
__global__ void gemv_bias_kernel(const float* __restrict__ b, const float* __restrict__ W,
                                 float* __restrict__ bias, int N)
{
    int j = blockIdx.x * 256 + threadIdx.x;
    float s = 0.f;
    for (int k = 0; k < 1024; k++) s += b[k] * W[(size_t)k * N + j];
    bias[j] = s;
}

// ---------------------------------------------------------------------------
// Attention: block = (b,h). 64 queries resident, 64-key chunks, online softmax.
// Inputs half, fp32 compute, output half.
// ---------------------------------------------------------------------------
#define SMEM_ATT (4 * 64 * 68 * 4)

__global__ __launch_bounds__(256) void attn_kernel(
    const __half* __restrict__ Q, const __half* __restrict__ KX,
    const __half* __restrict__ KL, __half* __restrict__ O)
{
    extern __shared__ __align__(16) float smA[];
    float* qs = smA;                 // [64][68]
    float* ks = smA + 64 * 68;
    float* vs = smA + 2 * 64 * 68;
    float* Ss = smA + 3 * 64 * 68;

    const int bh = blockIdx.x, b = bh >> 4, h = bh & 15;
    const int tid = threadIdx.x;
    const int ty = tid >> 4, tx = tid & 15;
    const int Q0 = ty << 2, X0 = tx << 2;

    const __half* Qb = Q + ((size_t)b * 64) * 1024 + h * 64;
#pragma unroll
    for (int rep = 0; rep < 4; rep++) {
        int id = tid + (rep << 8);
        int r = id >> 4, cc = (id & 15) << 2;
        const __half2* p = (const __half2*)(Qb + (size_t)r * 1024 + cc);
        float2 f0 = __half22float2(p[0]), f1 = __half22float2(p[1]);
        float4 v = make_float4(f0.x * 0.125f, f0.y * 0.125f, f1.x * 0.125f, f1.y * 0.125f);
        *(float4*)(qs + r * 68 + cc) = v;
    }

    float m[4], l[4], oacc[4][4];
#pragma unroll
    for (int i = 0; i < 4; i++) {
        m[i] = -1e30f; l[i] = 0.f;
#pragma unroll
        for (int j = 0; j < 4; j++) oacc[i][j] = 0.f;
    }

    for (int c = 0; c < 33; c++) {
        __syncthreads();
        const __half* base = (c < 32)
            ? KX + ((size_t)(b * 2048 + c * 64)) * 2048 + h * 64
            : KL + ((size_t)(b * 64)) * 2048 + h * 64;
#pragma unroll
        for (int rep = 0; rep < 4; rep++) {
            int id = tid + (rep << 8);
            int r = id >> 4, cc = (id & 15) << 2;
            const __half2* pk = (const __half2*)(base + (size_t)r * 2048 + cc);
            const __half2* pv = (const __half2*)(base + (size_t)r * 2048 + 1024 + cc);
            float2 k0 = __half22float2(pk[0]), k1 = __half22float2(pk[1]);
            float2 v0 = __half22float2(pv[0]), v1 = __half22float2(pv[1]);
            *(float4*)(ks + r * 68 + cc) = make_float4(k0.x, k0.y, k1.x, k1.y);
            *(float4*)(vs + r * 68 + cc) = make_float4(v0.x, v0.y, v1.x, v1.y);
        }
        __syncthreads();

        float s[4][4];
#pragma unroll
        for (int i = 0; i < 4; i++)
#pragma unroll
            for (int j = 0; j < 4; j++) s[i][j] = 0.f;
        for (int d = 0; d < 64; d += 4) {
            float4 qv[4], kv4[4];
#pragma unroll
            for (int i = 0; i < 4; i++) qv[i]  = *(const float4*)(qs + (Q0 + i) * 68 + d);
#pragma unroll
            for (int j = 0; j < 4; j++) kv4[j] = *(const float4*)(ks + (X0 + j) * 68 + d);
#pragma unroll
            for (int i = 0; i < 4; i++)
#pragma unroll
                for (int j = 0; j < 4; j++)
                    s[i][j] += qv[i].x * kv4[j].x + qv[i].y * kv4[j].y
                             + qv[i].z * kv4[j].z + qv[i].w * kv4[j].w;
        }
#pragma unroll
        for (int i = 0; i < 4; i++) {
            float mx = fmaxf(fmaxf(s[i][0], s[i][1]), fmaxf(s[i][2], s[i][3]));
#pragma unroll
            for (int o = 1; o < 16; o <<= 1) mx = fmaxf(mx, __shfl_xor_sync(0xffffffffu, mx, o));
            float mn = fmaxf(m[i], mx);
            float al = __expf(m[i] - mn);
            float ps = 0.f;
#pragma unroll
            for (int j = 0; j < 4; j++) {
                float p = __expf(s[i][j] - mn);
                Ss[(Q0 + i) * 68 + X0 + j] = p;
                ps += p;
            }
#pragma unroll
            for (int o = 1; o < 16; o <<= 1) ps += __shfl_xor_sync(0xffffffffu, ps, o);
            l[i] = l[i] * al + ps;
            m[i] = mn;
#pragma unroll
            for (int j = 0; j < 4; j++) oacc[i][j] *= al;
        }
        __syncthreads();

        for (int j = 0; j < 64; j += 4) {
            float4 vv[4], pv[4];
#pragma unroll
            for (int jj = 0; jj < 4; jj++) vv[jj] = *(const float4*)(vs + (j + jj) * 68 + X0);
#pragma unroll
            for (int i = 0; i < 4; i++)  pv[i] = *(const float4*)(Ss + (Q0 + i) * 68 + j);
#pragma unroll
            for (int i = 0; i < 4; i++) {
                oacc[i][0] += pv[i].x * vv[0].x + pv[i].y * vv[1].x + pv[i].z * vv[2].x + pv[i].w * vv[3].x;
                oacc[i][1] += pv[i].x * vv[0].y + pv[i].y * vv[1].y + pv[i].z * vv[2].y + pv[i].w * vv[3].y;
                oacc[i][2] += pv[i].x * vv[0].z + pv[i].y * vv[1].z + pv[i].z * vv[2].z + pv[i].w * vv[3].z;
                oacc[i][3] += pv[i].x * vv[0].w + pv[i].y * vv[1].w + pv[i].z * vv[2].w + pv[i].w * vv[3].w;
            }
        }
    }

#pragma unroll
    for (int i = 0; i < 4; i++) {
        float inv = 1.0f / l[i];
        __half* Ob = O + ((size_t)(b * 64 + Q0 + i)) * 1024 + h * 64 + X0;
        *(__half2*)(Ob)     = __floats2half2_rn(oacc[i][0] * inv, oacc[i][1] * inv);
        *(__half2*)(Ob + 2) = __floats2half2_rn(oacc[i][2] * inv, oacc[i][3] * inv);
    }
}

// ---------------------------------------------------------------------------
// Launch
// ---------------------------------------------------------------------------
extern "C" void kernel_launch(void* const* d_in, const int* in_sizes, int n_in,
                              void* d_out, int out_size)
{
    const float* x       = (const float*)d_in[0];
    const float* latents = (const float*)d_in[1];
    const float* n1s     = (const float*)d_in[2];
    const float* n1b     = (const float*)d_in[3];
    const float* n2s     = (const float*)d_in[4];
    const float* n2b     = (const float*)d_in[5];
    const float* Wq      = (const float*)d_in[6];
    const float* Wkv     = (const float*)d_in[7];
    const float* Wo      = (const float*)d_in[8];
    const float* ffs     = (const float*)d_in[9];
    const float* ffb     = (const float*)d_in[10];
    const float* W1      = (const float*)d_in[11];
    const float* W2      = (const float*)d_in[12];
    const float* projw   = (const float*)d_in[13];
    const float* projb   = (const float*)d_in[14];
    const float* outs    = (const float*)d_in[15];
    const float* outb    = (const float*)d_in[16];
    float* out = (float*)d_out;

    __half *z, *kvX, *kvL, *latH, *ltn, *q, *o, *hbuf;
    __half *WqT, *WoT, *prT, *WkvTs, *WkvTp, *W1T, *W2T;
    float *lat, *t2, *bkv;
    cudaGetSymbolAddress((void**)&z,    g_z);
    cudaGetSymbolAddress((void**)&kvX,  g_kvX);
    cudaGetSymbolAddress((void**)&kvL,  g_kvL);
    cudaGetSymbolAddress((void**)&lat,  g_lat);
    cudaGetSymbolAddress((void**)&latH, g_latH);
    cudaGetSymbolAddress((void**)&ltn,  g_ltn);
    cudaGetSymbolAddress((void**)&q,    g_q);
    cudaGetSymbolAddress((void**)&o,    g_o);
    cudaGetSymbolAddress((void**)&t2,   g_t2);
    cudaGetSymbolAddress((void**)&hbuf, g_h);
    cudaGetSymbolAddress((void**)&WqT,  g_WqT);
    cudaGetSymbolAddress((void**)&WoT,  g_WoT);
    cudaGetSymbolAddress((void**)&prT,  g_prT);
    cudaGetSymbolAddress((void**)&WkvTs,g_WkvTs);
    cudaGetSymbolAddress((void**)&WkvTp,g_WkvTp);
    cudaGetSymbolAddress((void**)&W1T,  g_W1T);
    cudaGetSymbolAddress((void**)&W2T,  g_W2T);
    cudaGetSymbolAddress((void**)&bkv,  g_bkv);

    cudaFuncSetAttribute(tc_gemm, cudaFuncAttributeMaxDynamicSharedMemorySize, SMEM_TC);
    cudaFuncSetAttribute(attn_kernel, cudaFuncAttributeMaxDynamicSharedMemorySize, SMEM_ATT);

    // ---- one-time prep ----
    bcast_kernel<<<8192, 256>>>(latents, lat);
    ln_kernel<<<65536, 256>>>(x, nullptr, z, nullptr, nullptr);   // unit-LN(x) -> half

    dim3 tb(32, 8);
    for (int i = 0; i < 2; i++) {
        transpose_kernel<<<dim3(32, 32), tb>>>(Wq  + (size_t)i*1048576, WqT  + (size_t)i*1048576, 1024, 1024, nullptr);
        transpose_kernel<<<dim3(64, 32), tb>>>(Wkv + (size_t)i*2097152, WkvTs+ (size_t)i*2097152, 1024, 2048, n1s + i*1024);
        transpose_kernel<<<dim3(64, 32), tb>>>(Wkv + (size_t)i*2097152, WkvTp+ (size_t)i*2097152, 1024, 2048, nullptr);
        transpose_kernel<<<dim3(32, 32), tb>>>(Wo  + (size_t)i*1048576, WoT  + (size_t)i*1048576, 1024, 1024, nullptr);
        transpose_kernel<<<dim3(128,32), tb>>>(W1  + (size_t)i*4194304, W1T  + (size_t)i*4194304, 1024, 4096, nullptr);
        transpose_kernel<<<dim3(32,128), tb>>>(W2  + (size_t)i*4194304, W2T  + (size_t)i*4194304, 4096, 1024, nullptr);
        gemv_bias_kernel<<<8, 256>>>(n1b + i*1024, Wkv + (size_t)i*2097152, bkv + i*2048, 2048);
    }
    transpose_kernel<<<dim3(32, 32), tb>>>(projw, prT, 1024, 1024, nullptr);

    // ---- layers ----
    for (int i = 0; i < 2; i++) {
        ln_kernel<<<2048, 256>>>(lat, nullptr, ltn, n2s + i*1024, n2b + i*1024);

        // q = ltn @ Wq  (half out)
        tc_gemm<<<dim3(8, 16), 256, SMEM_TC>>>(ltn, WqT + (size_t)i*1048576,
            nullptr, nullptr, nullptr, q, 2048, 1024, 1024, F_HALF);
        // kvX = z @ (s1*Wkv) + b1@Wkv  (half out)
        tc_gemm<<<dim3(16, 512), 256, SMEM_TC>>>(z, WkvTs + (size_t)i*2097152,
            nullptr, bkv + i*2048, nullptr, kvX, 65536, 2048, 1024, F_HALF);
        // kvL = ltn @ Wkv  (half out)
        tc_gemm<<<dim3(16, 16), 256, SMEM_TC>>>(ltn, WkvTp + (size_t)i*2097152,
            nullptr, nullptr, nullptr, kvL, 2048, 2048, 1024, F_HALF);

        attn_kernel<<<512, 256, SMEM_ATT>>>(q, kvX, kvL, o);

        // lat += o @ Wo  (float out)
        tc_gemm<<<dim3(8, 16), 256, SMEM_TC>>>(o, WoT + (size_t)i*1048576,
            lat, nullptr, lat, nullptr, 2048, 1024, 1024, F_RES);
        // h = gelu(LN_ff(lat) @ W1)  (half out)
        ln_kernel<<<2048, 256>>>(lat, nullptr, ltn, ffs + i*1024, ffb + i*1024);
        tc_gemm<<<dim3(32, 16), 256, SMEM_TC>>>(ltn, W1T + (size_t)i*4194304,
            nullptr, nullptr, nullptr, hbuf, 2048, 4096, 1024, F_GELU | F_HALF);
        // lat += h @ W2  (float out)
        tc_gemm<<<dim3(8, 16), 256, SMEM_TC>>>(hbuf, W2T + (size_t)i*4194304,
            lat, nullptr, lat, nullptr, 2048, 1024, 4096, F_RES);
    }

    // out = LN(lat @ proj_w + proj_b)
    f2h_kernel<<<8192, 256>>>(lat, latH);
    tc_gemm<<<dim3(8, 16), 256, SMEM_TC>>>(latH, prT, nullptr, projb, t2, nullptr,
                                           2048, 1024, 1024, 0);
    ln_kernel<<<2048, 256>>>(t2, out, nullptr, outs, outb);
}

// round 7
// speedup vs baseline: 6.1682x; 1.5988x over previous
#include <cuda_runtime.h>
#include <cuda_fp16.h>
#include <cstdint>
#include <math.h>

// B=32, N1=2048, DIM=1024, HEADS=16, DH=64, NQ=64, L=2, FF=4096
#define F_RES  1
#define F_GELU 4
#define F_HALF 8

// ---- scratch (device globals; allocation-free rule) ----
__device__ __half g_z   [67108864];   // 65536 x 1024  unit-LN(x)
__device__ __half g_kvX [268435456];  // 65536 x 4096  (both layers fused: layer l at col 2048l)
__device__ __half g_kvL [4194304];    // 2048  x 2048
__device__ float  g_lat [2097152];
__device__ __half g_latH[2097152];
__device__ __half g_ltn [2097152];
__device__ __half g_q   [2097152];
__device__ __half g_o   [2097152];
__device__ float  g_t2  [2097152];
__device__ __half g_h   [8388608];    // 2048 x 4096
__device__ __half g_WqT [2097152];    // 2 x [1024][1024]  (transposed [N][K])
__device__ __half g_WoT [2097152];
__device__ __half g_prT [1048576];
__device__ __half g_WkvTs[4194304];   // 2 x [2048][1024] scaled by norm1_s  (= [4096][1024])
__device__ __half g_WkvTp[4194304];   // 2 x [2048][1024]
__device__ __half g_W1T [8388608];    // 2 x [4096][1024]
__device__ __half g_W2T [8388608];    // 2 x [1024][4096]
__device__ float  g_bkv [4096];       // [4096] folded norm1_b @ Wkv (both layers)

// ---------------------------------------------------------------------------
__device__ __forceinline__ uint32_t s2u(const void* p) {
    return (uint32_t)__cvta_generic_to_shared(p);
}
__device__ __forceinline__ void cpasync16(uint32_t dst, const void* src) {
    asm volatile("cp.async.cg.shared.global [%0], [%1], 16;" :: "r"(dst), "l"(src) : "memory");
}
__device__ __forceinline__ float gelu_f(float x) {
    float x3 = x * x * x;
    return 0.5f * x * (1.0f + tanhf(0.7978845608028654f * (x + 0.044715f * x3)));
}
#define MMA16816(c, a0, a1, a2, a3, b0, b1) \
    asm volatile( \
        "mma.sync.aligned.m16n8k16.row.col.f32.f16.f16.f32 " \
        "{%0,%1,%2,%3}, {%4,%5,%6,%7}, {%8,%9}, {%0,%1,%2,%3};" \
        : "+f"((c)[0]), "+f"((c)[1]), "+f"((c)[2]), "+f"((c)[3]) \
        : "r"(a0), "r"(a1), "r"(a2), "r"(a3), "r"(b0), "r"(b1))

// ---------------------------------------------------------------------------
// fp16 mma GEMM: C[M,N] = A[M,K] @ Bt[N,K]^T  (+bias/gelu/residual)
// BM=128, BN=128, BK=32, 8 warps (2x4), warp tile 64x32, m16n8k16,
// 4-stage cp.async pipeline, 2 CTAs/SM.
// ---------------------------------------------------------------------------
#define AS_H      40                   // halves per smem row (80B stride)
#define TILE_H    (128 * AS_H)         // 5120 halves per operand tile
#define STG_H     (2 * TILE_H)
#define SMEM_TC   (4 * STG_H * 2)      // 81920 bytes

__device__ __forceinline__ void load_tile(
    __half* sm, int s, const __half* __restrict__ A, const __half* __restrict__ Bt,
    int K, size_t rowBase, size_t colBase, int t, int tid)
{
    __half* As = sm + s * STG_H;
    __half* Bs = As + TILE_H;
    const __half* Ag = A  + rowBase * K + t * 32;
    const __half* Bg = Bt + colBase * K + t * 32;
#pragma unroll
    for (int i = 0; i < 2; i++) {
        int ch = tid + (i << 8);
        int r = ch >> 2, c = ch & 3;
        cpasync16(s2u(As + r * AS_H + c * 8), Ag + (size_t)r * K + c * 8);
    }
#pragma unroll
    for (int i = 0; i < 2; i++) {
        int ch = tid + (i << 8);
        int r = ch >> 2, c = ch & 3;
        cpasync16(s2u(Bs + r * AS_H + c * 8), Bg + (size_t)r * K + c * 8);
    }
    asm volatile("cp.async.commit_group;" ::: "memory");
}

__global__ __launch_bounds__(256, 2) void tc_gemm(
    const __half* __restrict__ A, const __half* __restrict__ Bt,
    const float* __restrict__ Cin, const float* __restrict__ bias,
    float* __restrict__ C, __half* __restrict__ Ch,
    int M, int N, int K, int flags)
{
    extern __shared__ __align__(16) __half sm[];
    const int tid = threadIdx.x, wid = tid >> 5, lane = tid & 31;
    const int wm = wid & 1, wn = wid >> 1;
    const int gid = lane >> 2, tg = lane & 3;
    const size_t rowBase = (size_t)blockIdx.y * 128;
    const size_t colBase = (size_t)blockIdx.x * 128;

    float c[4][4][4];
#pragma unroll
    for (int mi = 0; mi < 4; mi++)
#pragma unroll
        for (int ni = 0; ni < 4; ni++)
#pragma unroll
            for (int k = 0; k < 4; k++) c[mi][ni][k] = 0.f;

    const int KT = K >> 5;
#pragma unroll
    for (int t = 0; t < 3; t++) load_tile(sm, t, A, Bt, K, rowBase, colBase, t, tid);

    for (int t = 0; t < KT; t++) {
        const int s = t & 3;
        asm volatile("cp.async.wait_group 2;" ::: "memory");
        __syncthreads();
        const int tp = t + 3;
        if (tp < KT) load_tile(sm, tp & 3, A, Bt, K, rowBase, colBase, tp, tid);

        const __half* As = sm + s * STG_H;
        const __half* Bs = As + TILE_H;
#pragma unroll
        for (int ks = 0; ks < 2; ks++) {
            const int k0 = ks << 4;
            uint32_t a[4][4], b[4][2];
#pragma unroll
            for (int mi = 0; mi < 4; mi++) {
                const __half* ap = As + (wm * 64 + mi * 16 + gid) * AS_H + k0 + 2 * tg;
                a[mi][0] = *(const uint32_t*)(ap);
                a[mi][1] = *(const uint32_t*)(ap + 8 * AS_H);
                a[mi][2] = *(const uint32_t*)(ap + 8);
                a[mi][3] = *(const uint32_t*)(ap + 8 * AS_H + 8);
            }
#pragma unroll
            for (int ni = 0; ni < 4; ni++) {
                const __half* bp = Bs + (wn * 32 + ni * 8 + gid) * AS_H + k0 + 2 * tg;
                b[ni][0] = *(const uint32_t*)(bp);
                b[ni][1] = *(const uint32_t*)(bp + 8);
            }
#pragma unroll
            for (int mi = 0; mi < 4; mi++)
#pragma unroll
                for (int ni = 0; ni < 4; ni++)
                    MMA16816(c[mi][ni], a[mi][0], a[mi][1], a[mi][2], a[mi][3],
                             b[ni][0], b[ni][1]);
        }
    }

#pragma unroll
    for (int mi = 0; mi < 4; mi++) {
        const size_t r0 = rowBase + wm * 64 + mi * 16 + gid;
        const size_t r1 = r0 + 8;
#pragma unroll
        for (int ni = 0; ni < 4; ni++) {
            const size_t col = colBase + wn * 32 + ni * 8 + tg * 2;
            float v0 = c[mi][ni][0], v1 = c[mi][ni][1];
            float v2 = c[mi][ni][2], v3 = c[mi][ni][3];
            if (bias) {
                float b0 = bias[col], b1 = bias[col + 1];
                v0 += b0; v1 += b1; v2 += b0; v3 += b1;
            }
            if (flags & F_GELU) {
                v0 = gelu_f(v0); v1 = gelu_f(v1); v2 = gelu_f(v2); v3 = gelu_f(v3);
            }
            if (flags & F_RES) {
                const float2 p0 = *(const float2*)(Cin + r0 * N + col);
                const float2 p1 = *(const float2*)(Cin + r1 * N + col);
                v0 += p0.x; v1 += p0.y; v2 += p1.x; v3 += p1.y;
            }
            if (flags & F_HALF) {
                *(__half2*)(Ch + r0 * N + col) = __floats2half2_rn(v0, v1);
                *(__half2*)(Ch + r1 * N + col) = __floats2half2_rn(v2, v3);
            } else {
                *(float2*)(C + r0 * N + col) = make_float2(v0, v1);
                *(float2*)(C + r1 * N + col) = make_float2(v2, v3);
            }
        }
    }
}

// ---------------------------------------------------------------------------
__global__ void bcast_kernel(const float* __restrict__ lat0, float* __restrict__ lat)
{
    int i = blockIdx.x * 256 + threadIdx.x;
    lat[i] = lat0[i & 65535];
}

__global__ void f2h_kernel(const float* __restrict__ in, __half* __restrict__ out)
{
    int i = blockIdx.x * 256 + threadIdx.x;
    out[i] = __float2half(in[i]);
}

// ---------------------------------------------------------------------------
// LayerNorm over 1024 cols, single pass. gs==null -> unit affine.
// ---------------------------------------------------------------------------
__global__ __launch_bounds__(256) void ln_kernel(
    const float* __restrict__ in, float* __restrict__ outF, __half* __restrict__ outH,
    const float* __restrict__ gs, const float* __restrict__ gb)
{
    __shared__ float r1[8], r2[8], bc[2];
    int r = blockIdx.x, tid = threadIdx.x;
    const float4 xv = ((const float4*)(in + (size_t)r * 1024))[tid];

    float s  = xv.x + xv.y + xv.z + xv.w;
    float s2 = xv.x*xv.x + xv.y*xv.y + xv.z*xv.z + xv.w*xv.w;
#pragma unroll
    for (int o = 16; o; o >>= 1) {
        s  += __shfl_xor_sync(0xffffffffu, s,  o);
        s2 += __shfl_xor_sync(0xffffffffu, s2, o);
    }
    if ((tid & 31) == 0) { r1[tid >> 5] = s; r2[tid >> 5] = s2; }
    __syncthreads();
    if (tid == 0) {
        float t1 = 0.f, t2 = 0.f;
#pragma unroll
        for (int i = 0; i < 8; i++) { t1 += r1[i]; t2 += r2[i]; }
        float m = t1 * (1.0f / 1024.0f);
        bc[0] = m;
        bc[1] = rsqrtf(t2 * (1.0f / 1024.0f) - m * m + 1e-5f);
    }
    __syncthreads();
    float mean = bc[0], inv = bc[1];

    float4 ov;
    ov.x = (xv.x - mean) * inv; ov.y = (xv.y - mean) * inv;
    ov.z = (xv.z - mean) * inv; ov.w = (xv.w - mean) * inv;
    if (gs) {
        const float4 sv = ((const float4*)gs)[tid];
        const float4 bv = ((const float4*)gb)[tid];
        ov.x = ov.x * sv.x + bv.x; ov.y = ov.y * sv.y + bv.y;
        ov.z = ov.z * sv.z + bv.z; ov.w = ov.w * sv.w + bv.w;
    }
    if (outH) {
        __half2* oh = (__half2*)(outH + (size_t)r * 1024);
        oh[tid * 2]     = __floats2half2_rn(ov.x, ov.y);
        oh[tid * 2 + 1] = __floats2half2_rn(ov.z, ov.w);
    } else {
        ((float4*)(outF + (size_t)r * 1024))[tid] = ov;
    }
}

// ---------------------------------------------------------------------------
// transpose: in[K][N] fp32 -> out[N][K] half, optional per-k scale
// ---------------------------------------------------------------------------
__global__ void transpose_kernel(const float* __restrict__ in, __half* __restrict__ out,
                                 int K, int N, const float* __restrict__ sc)
{
    __shared__ float t[32][33];
    int nb = blockIdx.x * 32, kb = blockIdx.y * 32;
    int tx = threadIdx.x, ty = threadIdx.y;
#pragma unroll
    for (int i = 0; i < 4; i++) {
        int k = kb + ty + i * 8;
        float v = in[(size_t)k * N + nb + tx];
        if (sc) v *= sc[k];
        t[ty + i * 8][tx] = v;
    }
    __syncthreads();
#pragma unroll
    for (int i = 0; i < 4; i++)
        out[(size_t)(nb + ty + i * 8) * K + kb + tx] = __float2half(t[tx][ty + i * 8]);
}

// ---------------------------------------------------------------------------
__global__ void gemv_bias_kernel(const float* __restrict__ b, const float* __restrict__ W,
                                 float* __restrict__ bias, int N)
{
    int j = blockIdx.x * 256 + threadIdx.x;
    float s = 0.f;
    for (int k = 0; k < 1024; k++) s += b[k] * W[(size_t)k * N + j];
    bias[j] = s;
}

// ---------------------------------------------------------------------------
// Attention on fp16 mma: block = (b,h), 128 threads = 4 warps, warp owns 16
// query rows. 64-key chunks, online softmax on fragments, P re-packed in
// registers for PV. KX row stride 4096 (fused layers), KL stride 2048.
// ---------------------------------------------------------------------------
#define SMEM_ATT (3 * 64 * 72 * 2)     // 27648 B: qs, ks, vsT

__global__ __launch_bounds__(128) void attn_kernel(
    const __half* __restrict__ Q, const __half* __restrict__ KX,
    const __half* __restrict__ KL, __half* __restrict__ O)
{
    extern __shared__ __align__(16) __half sa[];
    __half* qs = sa;                 // [64][72] k-major
    __half* ks = sa + 64 * 72;       // [key][72]
    __half* vs = sa + 2 * 64 * 72;   // transposed: [dim][72] cols=key

    const int bh = blockIdx.x, b = bh >> 4, h = bh & 15;
    const int tid = threadIdx.x, wid = tid >> 5, lane = tid & 31;
    const int gid = lane >> 2, tg = lane & 3;
    const int row0 = wid * 16 + gid;

    {   // load Q (64x64), scale by 0.125 (exact in half)
        const __half2 sc2 = __floats2half2_rn(0.125f, 0.125f);
        const __half* Qb = Q + ((size_t)b * 64) * 1024 + h * 64;
        for (int i = tid; i < 2048; i += 128) {
            int r = i >> 5, cc = i & 31;
            __half2 v = *(const __half2*)(Qb + (size_t)r * 1024 + cc * 2);
            *(__half2*)(qs + r * 72 + cc * 2) = __hmul2(v, sc2);
        }
    }

    float m0 = -1e30f, m1 = -1e30f, l0 = 0.f, l1 = 0.f;
    float oa[8][4];
#pragma unroll
    for (int ni = 0; ni < 8; ni++)
#pragma unroll
        for (int j = 0; j < 4; j++) oa[ni][j] = 0.f;

    for (int c = 0; c < 33; c++) {
        __syncthreads();
        const __half* base;
        size_t ld;
        if (c < 32) { base = KX + ((size_t)(b * 2048 + c * 64)) * 4096 + h * 64; ld = 4096; }
        else        { base = KL + ((size_t)(b * 64)) * 2048 + h * 64;            ld = 2048; }
        for (int i = tid; i < 512; i += 128) {        // K: 64 rows x 8 x 16B
            int r = i >> 3, cc = i & 7;
            *(uint4*)(ks + r * 72 + cc * 8) = *(const uint4*)(base + (size_t)r * ld + cc * 8);
        }
        for (int i = tid; i < 512; i += 128) {        // V transposed into vs
            int r = i >> 3, cc = i & 7;
            uint4 v4 = *(const uint4*)(base + (size_t)r * ld + 1024 + cc * 8);
            const __half* hv = (const __half*)&v4;
#pragma unroll
            for (int j = 0; j < 8; j++) vs[(cc * 8 + j) * 72 + r] = hv[j];
        }
        __syncthreads();

        // ---- QK: 16 x 64 scores per warp
        float sc[8][4];
#pragma unroll
        for (int ni = 0; ni < 8; ni++)
#pragma unroll
            for (int j = 0; j < 4; j++) sc[ni][j] = 0.f;
#pragma unroll
        for (int kk = 0; kk < 4; kk++) {
            const int k0 = kk << 4;
            const __half* ap = qs + row0 * 72 + k0 + 2 * tg;
            uint32_t a0 = *(const uint32_t*)(ap);
            uint32_t a1 = *(const uint32_t*)(ap + 8 * 72);
            uint32_t a2 = *(const uint32_t*)(ap + 8);
            uint32_t a3 = *(const uint32_t*)(ap + 8 * 72 + 8);
#pragma unroll
            for (int ni = 0; ni < 8; ni++) {
                const __half* bp = ks + (ni * 8 + gid) * 72 + k0 + 2 * tg;
                uint32_t b0 = *(const uint32_t*)(bp);
                uint32_t b1 = *(const uint32_t*)(bp + 8);
                MMA16816(sc[ni], a0, a1, a2, a3, b0, b1);
            }
        }

        // ---- online softmax (rows row0, row0+8)
        float mx0 = -1e30f, mx1 = -1e30f;
#pragma unroll
        for (int ni = 0; ni < 8; ni++) {
            mx0 = fmaxf(mx0, fmaxf(sc[ni][0], sc[ni][1]));
            mx1 = fmaxf(mx1, fmaxf(sc[ni][2], sc[ni][3]));
        }
        mx0 = fmaxf(mx0, __shfl_xor_sync(0xffffffffu, mx0, 1));
        mx0 = fmaxf(mx0, __shfl_xor_sync(0xffffffffu, mx0, 2));
        mx1 = fmaxf(mx1, __shfl_xor_sync(0xffffffffu, mx1, 1));
        mx1 = fmaxf(mx1, __shfl_xor_sync(0xffffffffu, mx1, 2));
        float mn0 = fmaxf(m0, mx0), mn1 = fmaxf(m1, mx1);
        float al0 = __expf(m0 - mn0), al1 = __expf(m1 - mn1);

        uint32_t pa[8][2];
        float ps0 = 0.f, ps1 = 0.f;
#pragma unroll
        for (int ni = 0; ni < 8; ni++) {
            float p0 = __expf(sc[ni][0] - mn0), p1 = __expf(sc[ni][1] - mn0);
            float p2 = __expf(sc[ni][2] - mn1), p3 = __expf(sc[ni][3] - mn1);
            ps0 += p0 + p1; ps1 += p2 + p3;
            __half2 h0 = __floats2half2_rn(p0, p1);
            __half2 h1 = __floats2half2_rn(p2, p3);
            pa[ni][0] = *(uint32_t*)&h0;
            pa[ni][1] = *(uint32_t*)&h1;
        }
        ps0 += __shfl_xor_sync(0xffffffffu, ps0, 1);
        ps0 += __shfl_xor_sync(0xffffffffu, ps0, 2);
        ps1 += __shfl_xor_sync(0xffffffffu, ps1, 1);
        ps1 += __shfl_xor_sync(0xffffffffu, ps1, 2);
        l0 = l0 * al0 + ps0; l1 = l1 * al1 + ps1;
        m0 = mn0; m1 = mn1;
#pragma unroll
        for (int ni = 0; ni < 8; ni++) {
            oa[ni][0] *= al0; oa[ni][1] *= al0;
            oa[ni][2] *= al1; oa[ni][3] *= al1;
        }

        // ---- PV: O[16x64] += P[16x64] @ V[64x64] (P a-frags from registers)
#pragma unroll
        for (int kk = 0; kk < 4; kk++) {
            uint32_t a0 = pa[2 * kk][0],     a1 = pa[2 * kk][1];
            uint32_t a2 = pa[2 * kk + 1][0], a3 = pa[2 * kk + 1][1];
#pragma unroll
            for (int ni = 0; ni < 8; ni++) {
                const __half* bp = vs + (ni * 8 + gid) * 72 + (kk << 4) + 2 * tg;
                uint32_t b0 = *(const uint32_t*)(bp);
                uint32_t b1 = *(const uint32_t*)(bp + 8);
                MMA16816(oa[ni], a0, a1, a2, a3, b0, b1);
            }
        }
    }

    float inv0 = 1.0f / l0, inv1 = 1.0f / l1;
    __half* Ob0 = O + ((size_t)(b * 64 + row0)) * 1024 + h * 64;
    __half* Ob1 = Ob0 + 8 * 1024;
#pragma unroll
    for (int ni = 0; ni < 8; ni++) {
        *(__half2*)(Ob0 + ni * 8 + 2 * tg) = __floats2half2_rn(oa[ni][0] * inv0, oa[ni][1] * inv0);
        *(__half2*)(Ob1 + ni * 8 + 2 * tg) = __floats2half2_rn(oa[ni][2] * inv1, oa[ni][3] * inv1);
    }
}

// ---------------------------------------------------------------------------
// Launch
// ---------------------------------------------------------------------------
extern "C" void kernel_launch(void* const* d_in, const int* in_sizes, int n_in,
                              void* d_out, int out_size)
{
    const float* x       = (const float*)d_in[0];
    const float* latents = (const float*)d_in[1];
    const float* n1s     = (const float*)d_in[2];
    const float* n1b     = (const float*)d_in[3];
    const float* n2s     = (const float*)d_in[4];
    const float* n2b     = (const float*)d_in[5];
    const float* Wq      = (const float*)d_in[6];
    const float* Wkv     = (const float*)d_in[7];
    const float* Wo      = (const float*)d_in[8];
    const float* ffs     = (const float*)d_in[9];
    const float* ffb     = (const float*)d_in[10];
    const float* W1      = (const float*)d_in[11];
    const float* W2      = (const float*)d_in[12];
    const float* projw   = (const float*)d_in[13];
    const float* projb   = (const float*)d_in[14];
    const float* outs    = (const float*)d_in[15];
    const float* outb    = (const float*)d_in[16];
    float* out = (float*)d_out;

    __half *z, *kvX, *kvL, *latH, *ltn, *q, *o, *hbuf;
    __half *WqT, *WoT, *prT, *WkvTs, *WkvTp, *W1T, *W2T;
    float *lat, *t2, *bkv;
    cudaGetSymbolAddress((void**)&z,    g_z);
    cudaGetSymbolAddress((void**)&kvX,  g_kvX);
    cudaGetSymbolAddress((void**)&kvL,  g_kvL);
    cudaGetSymbolAddress((void**)&lat,  g_lat);
    cudaGetSymbolAddress((void**)&latH, g_latH);
    cudaGetSymbolAddress((void**)&ltn,  g_ltn);
    cudaGetSymbolAddress((void**)&q,    g_q);
    cudaGetSymbolAddress((void**)&o,    g_o);
    cudaGetSymbolAddress((void**)&t2,   g_t2);
    cudaGetSymbolAddress((void**)&hbuf, g_h);
    cudaGetSymbolAddress((void**)&WqT,  g_WqT);
    cudaGetSymbolAddress((void**)&WoT,  g_WoT);
    cudaGetSymbolAddress((void**)&prT,  g_prT);
    cudaGetSymbolAddress((void**)&WkvTs,g_WkvTs);
    cudaGetSymbolAddress((void**)&WkvTp,g_WkvTp);
    cudaGetSymbolAddress((void**)&W1T,  g_W1T);
    cudaGetSymbolAddress((void**)&W2T,  g_W2T);
    cudaGetSymbolAddress((void**)&bkv,  g_bkv);

    cudaFuncSetAttribute(tc_gemm, cudaFuncAttributeMaxDynamicSharedMemorySize, SMEM_TC);
    cudaFuncSetAttribute(attn_kernel, cudaFuncAttributeMaxDynamicSharedMemorySize, SMEM_ATT);

    // ---- one-time prep ----
    bcast_kernel<<<8192, 256>>>(latents, lat);
    ln_kernel<<<65536, 256>>>(x, nullptr, z, nullptr, nullptr);   // unit-LN(x) -> half

    dim3 tb(32, 8);
    for (int i = 0; i < 2; i++) {
        transpose_kernel<<<dim3(32, 32), tb>>>(Wq  + (size_t)i*1048576, WqT  + (size_t)i*1048576, 1024, 1024, nullptr);
        transpose_kernel<<<dim3(64, 32), tb>>>(Wkv + (size_t)i*2097152, WkvTs+ (size_t)i*2097152, 1024, 2048, n1s + i*1024);
        transpose_kernel<<<dim3(64, 32), tb>>>(Wkv + (size_t)i*2097152, WkvTp+ (size_t)i*2097152, 1024, 2048, nullptr);
        transpose_kernel<<<dim3(32, 32), tb>>>(Wo  + (size_t)i*1048576, WoT  + (size_t)i*1048576, 1024, 1024, nullptr);
        transpose_kernel<<<dim3(128,32), tb>>>(W1  + (size_t)i*4194304, W1T  + (size_t)i*4194304, 1024, 4096, nullptr);
        transpose_kernel<<<dim3(32,128), tb>>>(W2  + (size_t)i*4194304, W2T  + (size_t)i*4194304, 4096, 1024, nullptr);
        gemv_bias_kernel<<<8, 256>>>(n1b + i*1024, Wkv + (size_t)i*2097152, bkv + i*2048, 2048);
    }
    transpose_kernel<<<dim3(32, 32), tb>>>(projw, prT, 1024, 1024, nullptr);

    // kvX for BOTH layers in one fused GEMM: [65536][4096]
    tc_gemm<<<dim3(32, 512), 256, SMEM_TC>>>(z, WkvTs,
        nullptr, bkv, nullptr, kvX, 65536, 4096, 1024, F_HALF);

    // ---- layers ----
    for (int i = 0; i < 2; i++) {
        ln_kernel<<<2048, 256>>>(lat, nullptr, ltn, n2s + i*1024, n2b + i*1024);

        // q = ltn @ Wq
        tc_gemm<<<dim3(8, 16), 256, SMEM_TC>>>(ltn, WqT + (size_t)i*1048576,
            nullptr, nullptr, nullptr, q, 2048, 1024, 1024, F_HALF);
        // kvL = ltn @ Wkv
        tc_gemm<<<dim3(16, 16), 256, SMEM_TC>>>(ltn, WkvTp + (size_t)i*2097152,
            nullptr, nullptr, nullptr, kvL, 2048, 2048, 1024, F_HALF);

        attn_kernel<<<512, 128, SMEM_ATT>>>(q, kvX + (size_t)i * 2048, kvL, o);

        // lat += o @ Wo
        tc_gemm<<<dim3(8, 16), 256, SMEM_TC>>>(o, WoT + (size_t)i*1048576,
            lat, nullptr, lat, nullptr, 2048, 1024, 1024, F_RES);
        // h = gelu(LN_ff(lat) @ W1)
        ln_kernel<<<2048, 256>>>(lat, nullptr, ltn, ffs + i*1024, ffb + i*1024);
        tc_gemm<<<dim3(32, 16), 256, SMEM_TC>>>(ltn, W1T + (size_t)i*4194304,
            nullptr, nullptr, nullptr, hbuf, 2048, 4096, 1024, F_GELU | F_HALF);
        // lat += h @ W2
        tc_gemm<<<dim3(8, 16), 256, SMEM_TC>>>(hbuf, W2T + (size_t)i*4194304,
            lat, nullptr, lat, nullptr, 2048, 1024, 4096, F_RES);
    }

    // out = LN(lat @ proj_w + proj_b)
    f2h_kernel<<<8192, 256>>>(lat, latH);
    tc_gemm<<<dim3(8, 16), 256, SMEM_TC>>>(latH, prT, nullptr, projb, t2, nullptr,
                                           2048, 1024, 1024, 0);
    ln_kernel<<<2048, 256>>>(t2, out, nullptr, outs, outb);
}

// round 8
// speedup vs baseline: 6.4623x; 1.0477x over previous
#include <cuda_runtime.h>
#include <cuda_fp16.h>
#include <cstdint>
#include <math.h>

// B=32, N1=2048, DIM=1024, HEADS=16, DH=64, NQ=64, L=2, FF=4096
#define F_RES  1
#define F_GELU 4
#define F_HALF 8

// ---- scratch (device globals; allocation-free rule) ----
__device__ __half g_z   [67108864];   // 65536 x 1024  unit-LN(x)
__device__ __half g_kvX [268435456];  // 65536 x 4096  (both layers fused)
__device__ __half g_kvL [4194304];    // 2048  x 2048
__device__ float  g_lat [2097152];
__device__ __half g_latH[2097152];
__device__ __half g_ltn [2097152];
__device__ __half g_q   [2097152];
__device__ __half g_o   [2097152];
__device__ float  g_t2  [2097152];
__device__ __half g_h   [8388608];    // 2048 x 4096
__device__ __half g_WqT [2097152];    // 2 x [1024][1024]  ([N][K])
__device__ __half g_WoT [2097152];
__device__ __half g_prT [1048576];
__device__ __half g_WkvTs[4194304];   // [4096][1024] scaled by norm1_s (2 layers)
__device__ __half g_WkvTp[4194304];
__device__ __half g_W1T [8388608];
__device__ __half g_W2T [8388608];
__device__ float  g_bkv [4096];

// ---------------------------------------------------------------------------
__device__ __forceinline__ uint32_t s2u(const void* p) {
    return (uint32_t)__cvta_generic_to_shared(p);
}
__device__ __forceinline__ void cpasync16(uint32_t dst, const void* src) {
    asm volatile("cp.async.cg.shared.global [%0], [%1], 16;" :: "r"(dst), "l"(src) : "memory");
}
__device__ __forceinline__ float gelu_f(float x) {
    float x3 = x * x * x;
    return 0.5f * x * (1.0f + tanhf(0.7978845608028654f * (x + 0.044715f * x3)));
}
#define MMA16816(c, a0, a1, a2, a3, b0, b1) \
    asm volatile( \
        "mma.sync.aligned.m16n8k16.row.col.f32.f16.f16.f32 " \
        "{%0,%1,%2,%3}, {%4,%5,%6,%7}, {%8,%9}, {%0,%1,%2,%3};" \
        : "+f"((c)[0]), "+f"((c)[1]), "+f"((c)[2]), "+f"((c)[3]) \
        : "r"(a0), "r"(a1), "r"(a2), "r"(a3), "r"(b0), "r"(b1))

// ---------------------------------------------------------------------------
// fp16 mma GEMM: C[M,N] = A[M,K] @ Bt[N,K]^T  (+bias/gelu/residual)
// BM=128, BN=128, BK=32, 4 warps (2x2), warp tile 64x64, m16n8k16,
// 4-stage cp.async pipeline, 2 CTAs/SM.
// ---------------------------------------------------------------------------
#define AS_H      40                   // halves per smem row (80B stride)
#define TILE_H    (128 * AS_H)
#define STG_H     (2 * TILE_H)
#define SMEM_TC   (4 * STG_H * 2)      // 81920 bytes

__device__ __forceinline__ void load_tile(
    __half* sm, int s, const __half* __restrict__ A, const __half* __restrict__ Bt,
    int K, size_t rowBase, size_t colBase, int t, int tid)
{
    __half* As = sm + s * STG_H;
    __half* Bs = As + TILE_H;
    const __half* Ag = A  + rowBase * K + t * 32;
    const __half* Bg = Bt + colBase * K + t * 32;
#pragma unroll
    for (int i = 0; i < 4; i++) {                 // A: 128 rows x 4 chunks(16B)
        int ch = tid + (i << 7);
        int r = ch >> 2, c = ch & 3;
        cpasync16(s2u(As + r * AS_H + c * 8), Ag + (size_t)r * K + c * 8);
    }
#pragma unroll
    for (int i = 0; i < 4; i++) {
        int ch = tid + (i << 7);
        int r = ch >> 2, c = ch & 3;
        cpasync16(s2u(Bs + r * AS_H + c * 8), Bg + (size_t)r * K + c * 8);
    }
    asm volatile("cp.async.commit_group;" ::: "memory");
}

__global__ __launch_bounds__(128, 2) void tc_gemm(
    const __half* __restrict__ A, const __half* __restrict__ Bt,
    const float* __restrict__ Cin, const float* __restrict__ bias,
    float* __restrict__ C, __half* __restrict__ Ch,
    int M, int N, int K, int flags)
{
    extern __shared__ __align__(16) __half sm[];
    const int tid = threadIdx.x, wid = tid >> 5, lane = tid & 31;
    const int wm = wid & 1, wn = wid >> 1;         // 2x2 warp grid
    const int gid = lane >> 2, tg = lane & 3;
    const size_t rowBase = (size_t)blockIdx.y * 128;
    const size_t colBase = (size_t)blockIdx.x * 128;

    float c[4][8][4];
#pragma unroll
    for (int mi = 0; mi < 4; mi++)
#pragma unroll
        for (int ni = 0; ni < 8; ni++)
#pragma unroll
            for (int k = 0; k < 4; k++) c[mi][ni][k] = 0.f;

    const int KT = K >> 5;
#pragma unroll
    for (int t = 0; t < 3; t++) load_tile(sm, t, A, Bt, K, rowBase, colBase, t, tid);

    for (int t = 0; t < KT; t++) {
        const int s = t & 3;
        asm volatile("cp.async.wait_group 2;" ::: "memory");
        __syncthreads();
        const int tp = t + 3;
        if (tp < KT) load_tile(sm, tp & 3, A, Bt, K, rowBase, colBase, tp, tid);

        const __half* As = sm + s * STG_H;
        const __half* Bs = As + TILE_H;
#pragma unroll
        for (int ks = 0; ks < 2; ks++) {
            const int k0 = ks << 4;
            uint32_t a[4][4], b[8][2];
#pragma unroll
            for (int mi = 0; mi < 4; mi++) {
                const __half* ap = As + (wm * 64 + mi * 16 + gid) * AS_H + k0 + 2 * tg;
                a[mi][0] = *(const uint32_t*)(ap);
                a[mi][1] = *(const uint32_t*)(ap + 8 * AS_H);
                a[mi][2] = *(const uint32_t*)(ap + 8);
                a[mi][3] = *(const uint32_t*)(ap + 8 * AS_H + 8);
            }
#pragma unroll
            for (int ni = 0; ni < 8; ni++) {
                const __half* bp = Bs + (wn * 64 + ni * 8 + gid) * AS_H + k0 + 2 * tg;
                b[ni][0] = *(const uint32_t*)(bp);
                b[ni][1] = *(const uint32_t*)(bp + 8);
            }
#pragma unroll
            for (int mi = 0; mi < 4; mi++)
#pragma unroll
                for (int ni = 0; ni < 8; ni++)
                    MMA16816(c[mi][ni], a[mi][0], a[mi][1], a[mi][2], a[mi][3],
                             b[ni][0], b[ni][1]);
        }
    }

    // epilogue
#pragma unroll
    for (int mi = 0; mi < 4; mi++) {
        const size_t r0 = rowBase + wm * 64 + mi * 16 + gid;
        const size_t r1 = r0 + 8;
#pragma unroll
        for (int ni = 0; ni < 8; ni++) {
            const size_t col = colBase + wn * 64 + ni * 8 + tg * 2;
            float v0 = c[mi][ni][0], v1 = c[mi][ni][1];
            float v2 = c[mi][ni][2], v3 = c[mi][ni][3];
            if (bias) {
                float b0 = bias[col], b1 = bias[col + 1];
                v0 += b0; v1 += b1; v2 += b0; v3 += b1;
            }
            if (flags & F_GELU) {
                v0 = gelu_f(v0); v1 = gelu_f(v1); v2 = gelu_f(v2); v3 = gelu_f(v3);
            }
            if (flags & F_RES) {
                const float2 p0 = *(const float2*)(Cin + r0 * N + col);
                const float2 p1 = *(const float2*)(Cin + r1 * N + col);
                v0 += p0.x; v1 += p0.y; v2 += p1.x; v3 += p1.y;
            }
            if (flags & F_HALF) {
                *(__half2*)(Ch + r0 * N + col) = __floats2half2_rn(v0, v1);
                *(__half2*)(Ch + r1 * N + col) = __floats2half2_rn(v2, v3);
            } else {
                *(float2*)(C + r0 * N + col) = make_float2(v0, v1);
                *(float2*)(C + r1 * N + col) = make_float2(v2, v3);
            }
        }
    }
}

// ---------------------------------------------------------------------------
__global__ void bcast_kernel(const float* __restrict__ lat0, float* __restrict__ lat)
{
    int i = blockIdx.x * 256 + threadIdx.x;
    lat[i] = lat0[i & 65535];
}

__global__ void f2h_kernel(const float* __restrict__ in, __half* __restrict__ out)
{
    int i = blockIdx.x * 256 + threadIdx.x;
    out[i] = __float2half(in[i]);
}

// ---------------------------------------------------------------------------
// LayerNorm over 1024 cols, single pass. gs==null -> unit affine.
// ---------------------------------------------------------------------------
__global__ __launch_bounds__(256) void ln_kernel(
    const float* __restrict__ in, float* __restrict__ outF, __half* __restrict__ outH,
    const float* __restrict__ gs, const float* __restrict__ gb)
{
    __shared__ float r1[8], r2[8], bc[2];
    int r = blockIdx.x, tid = threadIdx.x;
    const float4 xv = ((const float4*)(in + (size_t)r * 1024))[tid];

    float s  = xv.x + xv.y + xv.z + xv.w;
    float s2 = xv.x*xv.x + xv.y*xv.y + xv.z*xv.z + xv.w*xv.w;
#pragma unroll
    for (int o = 16; o; o >>= 1) {
        s  += __shfl_xor_sync(0xffffffffu, s,  o);
        s2 += __shfl_xor_sync(0xffffffffu, s2, o);
    }
    if ((tid & 31) == 0) { r1[tid >> 5] = s; r2[tid >> 5] = s2; }
    __syncthreads();
    if (tid == 0) {
        float t1 = 0.f, t2 = 0.f;
#pragma unroll
        for (int i = 0; i < 8; i++) { t1 += r1[i]; t2 += r2[i]; }
        float m = t1 * (1.0f / 1024.0f);
        bc[0] = m;
        bc[1] = rsqrtf(t2 * (1.0f / 1024.0f) - m * m + 1e-5f);
    }
    __syncthreads();
    float mean = bc[0], inv = bc[1];

    float4 ov;
    ov.x = (xv.x - mean) * inv; ov.y = (xv.y - mean) * inv;
    ov.z = (xv.z - mean) * inv; ov.w = (xv.w - mean) * inv;
    if (gs) {
        const float4 sv = ((const float4*)gs)[tid];
        const float4 bv = ((const float4*)gb)[tid];
        ov.x = ov.x * sv.x + bv.x; ov.y = ov.y * sv.y + bv.y;
        ov.z = ov.z * sv.z + bv.z; ov.w = ov.w * sv.w + bv.w;
    }
    if (outH) {
        __half2* oh = (__half2*)(outH + (size_t)r * 1024);
        oh[tid * 2]     = __floats2half2_rn(ov.x, ov.y);
        oh[tid * 2 + 1] = __floats2half2_rn(ov.z, ov.w);
    } else {
        ((float4*)(outF + (size_t)r * 1024))[tid] = ov;
    }
}

// ---------------------------------------------------------------------------
// transpose (batched over gridDim.z layers): in[z][K][N] fp32 -> out[z][N][K] half
// ---------------------------------------------------------------------------
__global__ void transpose_kernel(const float* __restrict__ in, __half* __restrict__ out,
                                 int K, int N, const float* __restrict__ sc)
{
    __shared__ float t[32][33];
    const size_t zo = (size_t)blockIdx.z * K * N;
    const float* inz = in + zo;
    __half* outz = out + zo;
    const float* scz = sc ? sc + (size_t)blockIdx.z * K : nullptr;
    int nb = blockIdx.x * 32, kb = blockIdx.y * 32;
    int tx = threadIdx.x, ty = threadIdx.y;
#pragma unroll
    for (int i = 0; i < 4; i++) {
        int k = kb + ty + i * 8;
        float v = inz[(size_t)k * N + nb + tx];
        if (scz) v *= scz[k];
        t[ty + i * 8][tx] = v;
    }
    __syncthreads();
#pragma unroll
    for (int i = 0; i < 4; i++)
        outz[(size_t)(nb + ty + i * 8) * K + kb + tx] = __float2half(t[tx][ty + i * 8]);
}

// ---------------------------------------------------------------------------
__global__ void gemv_bias_kernel(const float* __restrict__ b, const float* __restrict__ W,
                                 float* __restrict__ bias, int N)
{
    int j = blockIdx.x * 256 + threadIdx.x;
    const float* Wz = W + (size_t)blockIdx.y * 1024 * N;
    const float* bz = b + (size_t)blockIdx.y * 1024;
    float s = 0.f;
    for (int k = 0; k < 1024; k++) s += bz[k] * Wz[(size_t)k * N + j];
    bias[blockIdx.y * N + j] = s;
}

// ---------------------------------------------------------------------------
// Attention on fp16 mma: block = (b,h), 128 threads = 4 warps, warp owns 16
// query rows. 64-key chunks, online softmax on fragments, P re-packed in
// registers for PV. KX row stride 4096 (fused layers), KL stride 2048.
// ---------------------------------------------------------------------------
#define SMEM_ATT (3 * 64 * 72 * 2)

__global__ __launch_bounds__(128) void attn_kernel(
    const __half* __restrict__ Q, const __half* __restrict__ KX,
    const __half* __restrict__ KL, __half* __restrict__ O)
{
    extern __shared__ __align__(16) __half sa[];
    __half* qs = sa;                 // [64][72] k-major
    __half* ks = sa + 64 * 72;       // [key][72]
    __half* vs = sa + 2 * 64 * 72;   // transposed: [dim][72] cols=key

    const int bh = blockIdx.x, b = bh >> 4, h = bh & 15;
    const int tid = threadIdx.x, wid = tid >> 5, lane = tid & 31;
    const int gid = lane >> 2, tg = lane & 3;
    const int row0 = wid * 16 + gid;

    {
        const __half2 sc2 = __floats2half2_rn(0.125f, 0.125f);
        const __half* Qb = Q + ((size_t)b * 64) * 1024 + h * 64;
        for (int i = tid; i < 2048; i += 128) {
            int r = i >> 5, cc = i & 31;
            __half2 v = *(const __half2*)(Qb + (size_t)r * 1024 + cc * 2);
            *(__half2*)(qs + r * 72 + cc * 2) = __hmul2(v, sc2);
        }
    }

    float m0 = -1e30f, m1 = -1e30f, l0 = 0.f, l1 = 0.f;
    float oa[8][4];
#pragma unroll
    for (int ni = 0; ni < 8; ni++)
#pragma unroll
        for (int j = 0; j < 4; j++) oa[ni][j] = 0.f;

    for (int c = 0; c < 33; c++) {
        __syncthreads();
        const __half* base;
        size_t ld;
        if (c < 32) { base = KX + ((size_t)(b * 2048 + c * 64)) * 4096 + h * 64; ld = 4096; }
        else        { base = KL + ((size_t)(b * 64)) * 2048 + h * 64;            ld = 2048; }
        for (int i = tid; i < 512; i += 128) {
            int r = i >> 3, cc = i & 7;
            *(uint4*)(ks + r * 72 + cc * 8) = *(const uint4*)(base + (size_t)r * ld + cc * 8);
        }
        for (int i = tid; i < 512; i += 128) {
            int r = i >> 3, cc = i & 7;
            uint4 v4 = *(const uint4*)(base + (size_t)r * ld + 1024 + cc * 8);
            const __half* hv = (const __half*)&v4;
#pragma unroll
            for (int j = 0; j < 8; j++) vs[(cc * 8 + j) * 72 + r] = hv[j];
        }
        __syncthreads();

        float sc[8][4];
#pragma unroll
        for (int ni = 0; ni < 8; ni++)
#pragma unroll
            for (int j = 0; j < 4; j++) sc[ni][j] = 0.f;
#pragma unroll
        for (int kk = 0; kk < 4; kk++) {
            const int k0 = kk << 4;
            const __half* ap = qs + row0 * 72 + k0 + 2 * tg;
            uint32_t a0 = *(const uint32_t*)(ap);
            uint32_t a1 = *(const uint32_t*)(ap + 8 * 72);
            uint32_t a2 = *(const uint32_t*)(ap + 8);
            uint32_t a3 = *(const uint32_t*)(ap + 8 * 72 + 8);
#pragma unroll
            for (int ni = 0; ni < 8; ni++) {
                const __half* bp = ks + (ni * 8 + gid) * 72 + k0 + 2 * tg;
                uint32_t b0 = *(const uint32_t*)(bp);
                uint32_t b1 = *(const uint32_t*)(bp + 8);
                MMA16816(sc[ni], a0, a1, a2, a3, b0, b1);
            }
        }

        float mx0 = -1e30f, mx1 = -1e30f;
#pragma unroll
        for (int ni = 0; ni < 8; ni++) {
            mx0 = fmaxf(mx0, fmaxf(sc[ni][0], sc[ni][1]));
            mx1 = fmaxf(mx1, fmaxf(sc[ni][2], sc[ni][3]));
        }
        mx0 = fmaxf(mx0, __shfl_xor_sync(0xffffffffu, mx0, 1));
        mx0 = fmaxf(mx0, __shfl_xor_sync(0xffffffffu, mx0, 2));
        mx1 = fmaxf(mx1, __shfl_xor_sync(0xffffffffu, mx1, 1));
        mx1 = fmaxf(mx1, __shfl_xor_sync(0xffffffffu, mx1, 2));
        float mn0 = fmaxf(m0, mx0), mn1 = fmaxf(m1, mx1);
        float al0 = __expf(m0 - mn0), al1 = __expf(m1 - mn1);

        uint32_t pa[8][2];
        float ps0 = 0.f, ps1 = 0.f;
#pragma unroll
        for (int ni = 0; ni < 8; ni++) {
            float p0 = __expf(sc[ni][0] - mn0), p1 = __expf(sc[ni][1] - mn0);
            float p2 = __expf(sc[ni][2] - mn1), p3 = __expf(sc[ni][3] - mn1);
            ps0 += p0 + p1; ps1 += p2 + p3;
            __half2 h0 = __floats2half2_rn(p0, p1);
            __half2 h1 = __floats2half2_rn(p2, p3);
            pa[ni][0] = *(uint32_t*)&h0;
            pa[ni][1] = *(uint32_t*)&h1;
        }
        ps0 += __shfl_xor_sync(0xffffffffu, ps0, 1);
        ps0 += __shfl_xor_sync(0xffffffffu, ps0, 2);
        ps1 += __shfl_xor_sync(0xffffffffu, ps1, 1);
        ps1 += __shfl_xor_sync(0xffffffffu, ps1, 2);
        l0 = l0 * al0 + ps0; l1 = l1 * al1 + ps1;
        m0 = mn0; m1 = mn1;
#pragma unroll
        for (int ni = 0; ni < 8; ni++) {
            oa[ni][0] *= al0; oa[ni][1] *= al0;
            oa[ni][2] *= al1; oa[ni][3] *= al1;
        }

#pragma unroll
        for (int kk = 0; kk < 4; kk++) {
            uint32_t a0 = pa[2 * kk][0],     a1 = pa[2 * kk][1];
            uint32_t a2 = pa[2 * kk + 1][0], a3 = pa[2 * kk + 1][1];
#pragma unroll
            for (int ni = 0; ni < 8; ni++) {
                const __half* bp = vs + (ni * 8 + gid) * 72 + (kk << 4) + 2 * tg;
                uint32_t b0 = *(const uint32_t*)(bp);
                uint32_t b1 = *(const uint32_t*)(bp + 8);
                MMA16816(oa[ni], a0, a1, a2, a3, b0, b1);
            }
        }
    }

    float inv0 = 1.0f / l0, inv1 = 1.0f / l1;
    __half* Ob0 = O + ((size_t)(b * 64 + row0)) * 1024 + h * 64;
    __half* Ob1 = Ob0 + 8 * 1024;
#pragma unroll
    for (int ni = 0; ni < 8; ni++) {
        *(__half2*)(Ob0 + ni * 8 + 2 * tg) = __floats2half2_rn(oa[ni][0] * inv0, oa[ni][1] * inv0);
        *(__half2*)(Ob1 + ni * 8 + 2 * tg) = __floats2half2_rn(oa[ni][2] * inv1, oa[ni][3] * inv1);
    }
}

// ---------------------------------------------------------------------------
// Launch
// ---------------------------------------------------------------------------
extern "C" void kernel_launch(void* const* d_in, const int* in_sizes, int n_in,
                              void* d_out, int out_size)
{
    const float* x       = (const float*)d_in[0];
    const float* latents = (const float*)d_in[1];
    const float* n1s     = (const float*)d_in[2];
    const float* n1b     = (const float*)d_in[3];
    const float* n2s     = (const float*)d_in[4];
    const float* n2b     = (const float*)d_in[5];
    const float* Wq      = (const float*)d_in[6];
    const float* Wkv     = (const float*)d_in[7];
    const float* Wo      = (const float*)d_in[8];
    const float* ffs     = (const float*)d_in[9];
    const float* ffb     = (const float*)d_in[10];
    const float* W1      = (const float*)d_in[11];
    const float* W2      = (const float*)d_in[12];
    const float* projw   = (const float*)d_in[13];
    const float* projb   = (const float*)d_in[14];
    const float* outs    = (const float*)d_in[15];
    const float* outb    = (const float*)d_in[16];
    float* out = (float*)d_out;

    __half *z, *kvX, *kvL, *latH, *ltn, *q, *o, *hbuf;
    __half *WqT, *WoT, *prT, *WkvTs, *WkvTp, *W1T, *W2T;
    float *lat, *t2, *bkv;
    cudaGetSymbolAddress((void**)&z,    g_z);
    cudaGetSymbolAddress((void**)&kvX,  g_kvX);
    cudaGetSymbolAddress((void**)&kvL,  g_kvL);
    cudaGetSymbolAddress((void**)&lat,  g_lat);
    cudaGetSymbolAddress((void**)&latH, g_latH);
    cudaGetSymbolAddress((void**)&ltn,  g_ltn);
    cudaGetSymbolAddress((void**)&q,    g_q);
    cudaGetSymbolAddress((void**)&o,    g_o);
    cudaGetSymbolAddress((void**)&t2,   g_t2);
    cudaGetSymbolAddress((void**)&hbuf, g_h);
    cudaGetSymbolAddress((void**)&WqT,  g_WqT);
    cudaGetSymbolAddress((void**)&WoT,  g_WoT);
    cudaGetSymbolAddress((void**)&prT,  g_prT);
    cudaGetSymbolAddress((void**)&WkvTs,g_WkvTs);
    cudaGetSymbolAddress((void**)&WkvTp,g_WkvTp);
    cudaGetSymbolAddress((void**)&W1T,  g_W1T);
    cudaGetSymbolAddress((void**)&W2T,  g_W2T);
    cudaGetSymbolAddress((void**)&bkv,  g_bkv);

    cudaFuncSetAttribute(tc_gemm, cudaFuncAttributeMaxDynamicSharedMemorySize, SMEM_TC);
    cudaFuncSetAttribute(attn_kernel, cudaFuncAttributeMaxDynamicSharedMemorySize, SMEM_ATT);

    // ---- one-time prep ----
    bcast_kernel<<<8192, 256>>>(latents, lat);
    ln_kernel<<<65536, 256>>>(x, nullptr, z, nullptr, nullptr);

    dim3 tb(32, 8);
    transpose_kernel<<<dim3(32, 32, 2), tb>>>(Wq,  WqT,  1024, 1024, nullptr);
    transpose_kernel<<<dim3(64, 32, 2), tb>>>(Wkv, WkvTs, 1024, 2048, n1s);
    transpose_kernel<<<dim3(64, 32, 2), tb>>>(Wkv, WkvTp, 1024, 2048, nullptr);
    transpose_kernel<<<dim3(32, 32, 2), tb>>>(Wo,  WoT,  1024, 1024, nullptr);
    transpose_kernel<<<dim3(128,32, 2), tb>>>(W1,  W1T,  1024, 4096, nullptr);
    transpose_kernel<<<dim3(32,128, 2), tb>>>(W2,  W2T,  4096, 1024, nullptr);
    transpose_kernel<<<dim3(32, 32, 1), tb>>>(projw, prT, 1024, 1024, nullptr);
    gemv_bias_kernel<<<dim3(8, 2), 256>>>(n1b, Wkv, bkv, 2048);

    // kvX for BOTH layers in one fused GEMM: [65536][4096]
    tc_gemm<<<dim3(32, 512), 128, SMEM_TC>>>(z, WkvTs,
        nullptr, bkv, nullptr, kvX, 65536, 4096, 1024, F_HALF);

    // ---- layers ----
    for (int i = 0; i < 2; i++) {
        ln_kernel<<<2048, 256>>>(lat, nullptr, ltn, n2s + i*1024, n2b + i*1024);

        tc_gemm<<<dim3(8, 16), 128, SMEM_TC>>>(ltn, WqT + (size_t)i*1048576,
            nullptr, nullptr, nullptr, q, 2048, 1024, 1024, F_HALF);
        tc_gemm<<<dim3(16, 16), 128, SMEM_TC>>>(ltn, WkvTp + (size_t)i*2097152,
            nullptr, nullptr, nullptr, kvL, 2048, 2048, 1024, F_HALF);

        attn_kernel<<<512, 128, SMEM_ATT>>>(q, kvX + (size_t)i * 2048, kvL, o);

        tc_gemm<<<dim3(8, 16), 128, SMEM_TC>>>(o, WoT + (size_t)i*1048576,
            lat, nullptr, lat, nullptr, 2048, 1024, 1024, F_RES);
        ln_kernel<<<2048, 256>>>(lat, nullptr, ltn, ffs + i*1024, ffb + i*1024);
        tc_gemm<<<dim3(32, 16), 128, SMEM_TC>>>(ltn, W1T + (size_t)i*4194304,
            nullptr, nullptr, nullptr, hbuf, 2048, 4096, 1024, F_GELU | F_HALF);
        tc_gemm<<<dim3(8, 16), 128, SMEM_TC>>>(hbuf, W2T + (size_t)i*4194304,
            lat, nullptr, lat, nullptr, 2048, 1024, 4096, F_RES);
    }

    // out = LN(lat @ proj_w + proj_b)
    f2h_kernel<<<8192, 256>>>(lat, latH);
    tc_gemm<<<dim3(8, 16), 128, SMEM_TC>>>(latH, prT, nullptr, projb, t2, nullptr,
                                           2048, 1024, 1024, 0);
    ln_kernel<<<2048, 256>>>(t2, out, nullptr, outs, outb);
}

// round 9
// speedup vs baseline: 6.5922x; 1.0201x over previous
#include <cuda_runtime.h>
#include <cuda_fp16.h>
#include <cstdint>
#include <math.h>

// B=32, N1=2048, DIM=1024, HEADS=16, DH=64, NQ=64, L=2, FF=4096
#define F_RES  1
#define F_GELU 4
#define F_HALF 8
#define F_BOTH 16

// ---- scratch (device globals; allocation-free rule) ----
__device__ __half g_z   [67108864];   // 65536 x 1024  unit-LN(x)
__device__ __half g_kvX [268435456];  // 65536 x 4096  (both layers fused)
__device__ __half g_kvL [4194304];    // 2048  x 2048
__device__ float  g_lat [2097152];
__device__ __half g_latH[2097152];
__device__ __half g_ltn [2097152];
__device__ __half g_q   [2097152];
__device__ __half g_o   [2097152];
__device__ float  g_t2  [2097152];
__device__ __half g_h   [8388608];    // 2048 x 4096
__device__ __half g_WqT [2097152];    // 2 x [1024][1024]  ([N][K])
__device__ __half g_WoT [2097152];
__device__ __half g_prT [1048576];
__device__ __half g_WkvTs[4194304];   // [4096][1024] scaled by norm1_s (2 layers)
__device__ __half g_WkvTp[4194304];
__device__ __half g_W1T [8388608];
__device__ __half g_W2T [8388608];
__device__ float  g_bkv [4096];

// ---------------------------------------------------------------------------
__device__ __forceinline__ uint32_t s2u(const void* p) {
    return (uint32_t)__cvta_generic_to_shared(p);
}
__device__ __forceinline__ void cpasync16(uint32_t dst, const void* src) {
    asm volatile("cp.async.cg.shared.global [%0], [%1], 16;" :: "r"(dst), "l"(src) : "memory");
}
__device__ __forceinline__ float gelu_f(float x) {
    float x3 = x * x * x;
    return 0.5f * x * (1.0f + tanhf(0.7978845608028654f * (x + 0.044715f * x3)));
}
#define MMA16816(c, a0, a1, a2, a3, b0, b1) \
    asm volatile( \
        "mma.sync.aligned.m16n8k16.row.col.f32.f16.f16.f32 " \
        "{%0,%1,%2,%3}, {%4,%5,%6,%7}, {%8,%9}, {%0,%1,%2,%3};" \
        : "+f"((c)[0]), "+f"((c)[1]), "+f"((c)[2]), "+f"((c)[3]) \
        : "r"(a0), "r"(a1), "r"(a2), "r"(a3), "r"(b0), "r"(b1))

// ---------------------------------------------------------------------------
// fp16 mma GEMM: C[M,N] = A[M,K] @ Bt[N,K]^T  (+bias/gelu/residual)
// BM=128, BN=128, BK=32, 4 warps (2x2), warp tile 64x64, m16n8k16,
// 4-stage cp.async pipeline, 2 CTAs/SM.
// ---------------------------------------------------------------------------
#define AS_H      40
#define TILE_H    (128 * AS_H)
#define STG_H     (2 * TILE_H)
#define SMEM_TC   (4 * STG_H * 2)      // 81920 bytes

__device__ __forceinline__ void load_tile(
    __half* sm, int s, const __half* __restrict__ A, const __half* __restrict__ Bt,
    int K, size_t rowBase, size_t colBase, int t, int tid)
{
    __half* As = sm + s * STG_H;
    __half* Bs = As + TILE_H;
    const __half* Ag = A  + rowBase * K + t * 32;
    const __half* Bg = Bt + colBase * K + t * 32;
#pragma unroll
    for (int i = 0; i < 4; i++) {
        int ch = tid + (i << 7);
        int r = ch >> 2, c = ch & 3;
        cpasync16(s2u(As + r * AS_H + c * 8), Ag + (size_t)r * K + c * 8);
    }
#pragma unroll
    for (int i = 0; i < 4; i++) {
        int ch = tid + (i << 7);
        int r = ch >> 2, c = ch & 3;
        cpasync16(s2u(Bs + r * AS_H + c * 8), Bg + (size_t)r * K + c * 8);
    }
    asm volatile("cp.async.commit_group;" ::: "memory");
}

__global__ __launch_bounds__(128, 2) void tc_gemm(
    const __half* __restrict__ A, const __half* __restrict__ Bt,
    const float* __restrict__ Cin, const float* __restrict__ bias,
    float* __restrict__ C, __half* __restrict__ Ch,
    int M, int N, int K, int flags)
{
    extern __shared__ __align__(16) __half sm[];
    const int tid = threadIdx.x, wid = tid >> 5, lane = tid & 31;
    const int wm = wid & 1, wn = wid >> 1;
    const int gid = lane >> 2, tg = lane & 3;
    const size_t rowBase = (size_t)blockIdx.y * 128;
    const size_t colBase = (size_t)blockIdx.x * 128;

    float c[4][8][4];
#pragma unroll
    for (int mi = 0; mi < 4; mi++)
#pragma unroll
        for (int ni = 0; ni < 8; ni++)
#pragma unroll
            for (int k = 0; k < 4; k++) c[mi][ni][k] = 0.f;

    const int KT = K >> 5;
#pragma unroll
    for (int t = 0; t < 3; t++) load_tile(sm, t, A, Bt, K, rowBase, colBase, t, tid);

    for (int t = 0; t < KT; t++) {
        const int s = t & 3;
        asm volatile("cp.async.wait_group 2;" ::: "memory");
        __syncthreads();
        const int tp = t + 3;
        if (tp < KT) load_tile(sm, tp & 3, A, Bt, K, rowBase, colBase, tp, tid);

        const __half* As = sm + s * STG_H;
        const __half* Bs = As + TILE_H;
#pragma unroll
        for (int ks = 0; ks < 2; ks++) {
            const int k0 = ks << 4;
            uint32_t a[4][4], b[8][2];
#pragma unroll
            for (int mi = 0; mi < 4; mi++) {
                const __half* ap = As + (wm * 64 + mi * 16 + gid) * AS_H + k0 + 2 * tg;
                a[mi][0] = *(const uint32_t*)(ap);
                a[mi][1] = *(const uint32_t*)(ap + 8 * AS_H);
                a[mi][2] = *(const uint32_t*)(ap + 8);
                a[mi][3] = *(const uint32_t*)(ap + 8 * AS_H + 8);
            }
#pragma unroll
            for (int ni = 0; ni < 8; ni++) {
                const __half* bp = Bs + (wn * 64 + ni * 8 + gid) * AS_H + k0 + 2 * tg;
                b[ni][0] = *(const uint32_t*)(bp);
                b[ni][1] = *(const uint32_t*)(bp + 8);
            }
#pragma unroll
            for (int mi = 0; mi < 4; mi++)
#pragma unroll
                for (int ni = 0; ni < 8; ni++)
                    MMA16816(c[mi][ni], a[mi][0], a[mi][1], a[mi][2], a[mi][3],
                             b[ni][0], b[ni][1]);
        }
    }

    // epilogue
#pragma unroll
    for (int mi = 0; mi < 4; mi++) {
        const size_t r0 = rowBase + wm * 64 + mi * 16 + gid;
        const size_t r1 = r0 + 8;
#pragma unroll
        for (int ni = 0; ni < 8; ni++) {
            const size_t col = colBase + wn * 64 + ni * 8 + tg * 2;
            float v0 = c[mi][ni][0], v1 = c[mi][ni][1];
            float v2 = c[mi][ni][2], v3 = c[mi][ni][3];
            if (bias) {
                float b0 = bias[col], b1 = bias[col + 1];
                v0 += b0; v1 += b1; v2 += b0; v3 += b1;
            }
            if (flags & F_GELU) {
                v0 = gelu_f(v0); v1 = gelu_f(v1); v2 = gelu_f(v2); v3 = gelu_f(v3);
            }
            if (flags & F_RES) {
                const float2 p0 = *(const float2*)(Cin + r0 * N + col);
                const float2 p1 = *(const float2*)(Cin + r1 * N + col);
                v0 += p0.x; v1 += p0.y; v2 += p1.x; v3 += p1.y;
            }
            if (flags & F_HALF) {
                *(__half2*)(Ch + r0 * N + col) = __floats2half2_rn(v0, v1);
                *(__half2*)(Ch + r1 * N + col) = __floats2half2_rn(v2, v3);
            } else {
                *(float2*)(C + r0 * N + col) = make_float2(v0, v1);
                *(float2*)(C + r1 * N + col) = make_float2(v2, v3);
                if (flags & F_BOTH) {
                    *(__half2*)(Ch + r0 * N + col) = __floats2half2_rn(v0, v1);
                    *(__half2*)(Ch + r1 * N + col) = __floats2half2_rn(v2, v3);
                }
            }
        }
    }
}

// ---------------------------------------------------------------------------
__global__ void bcast_kernel(const float* __restrict__ lat0, float* __restrict__ lat)
{
    int i = blockIdx.x * 256 + threadIdx.x;
    lat[i] = lat0[i & 65535];
}

// ---------------------------------------------------------------------------
// Warp-per-row LayerNorm over 1024 cols. 128 threads = 4 rows/block.
// No smem, no __syncthreads; 8 float4 per lane, shfl reduction.
// gs==null -> unit affine. Writes half (outH) or float (outF).
// ---------------------------------------------------------------------------
__global__ __launch_bounds__(128) void lnw_kernel(
    const float* __restrict__ in, float* __restrict__ outF, __half* __restrict__ outH,
    const float* __restrict__ gs, const float* __restrict__ gb)
{
    const int row = blockIdx.x * 4 + (threadIdx.x >> 5);
    const int lane = threadIdx.x & 31;
    const float4* ip = (const float4*)(in + (size_t)row * 1024);

    float4 v[8];
    float s = 0.f, s2 = 0.f;
#pragma unroll
    for (int j = 0; j < 8; j++) {
        v[j] = ip[lane + 32 * j];
        s  += v[j].x + v[j].y + v[j].z + v[j].w;
        s2 += v[j].x*v[j].x + v[j].y*v[j].y + v[j].z*v[j].z + v[j].w*v[j].w;
    }
#pragma unroll
    for (int o = 16; o; o >>= 1) {
        s  += __shfl_xor_sync(0xffffffffu, s,  o);
        s2 += __shfl_xor_sync(0xffffffffu, s2, o);
    }
    const float mean = s * (1.0f / 1024.0f);
    const float inv  = rsqrtf(s2 * (1.0f / 1024.0f) - mean * mean + 1e-5f);

#pragma unroll
    for (int j = 0; j < 8; j++) {
        const int idx = lane + 32 * j;
        float4 ov;
        ov.x = (v[j].x - mean) * inv; ov.y = (v[j].y - mean) * inv;
        ov.z = (v[j].z - mean) * inv; ov.w = (v[j].w - mean) * inv;
        if (gs) {
            const float4 sv = ((const float4*)gs)[idx];
            const float4 bv = ((const float4*)gb)[idx];
            ov.x = ov.x * sv.x + bv.x; ov.y = ov.y * sv.y + bv.y;
            ov.z = ov.z * sv.z + bv.z; ov.w = ov.w * sv.w + bv.w;
        }
        if (outH) {
            __half2 h0 = __floats2half2_rn(ov.x, ov.y);
            __half2 h1 = __floats2half2_rn(ov.z, ov.w);
            uint2 pk;
            pk.x = *(uint32_t*)&h0; pk.y = *(uint32_t*)&h1;
            ((uint2*)(outH + (size_t)row * 1024))[idx] = pk;
        } else {
            ((float4*)(outF + (size_t)row * 1024))[idx] = ov;
        }
    }
}

// ---------------------------------------------------------------------------
// transpose (batched over gridDim.z): in[z][K][N] fp32 -> out[z][N][K] half
// ---------------------------------------------------------------------------
__global__ void transpose_kernel(const float* __restrict__ in, __half* __restrict__ out,
                                 int K, int N, const float* __restrict__ sc)
{
    __shared__ float t[32][33];
    const size_t zo = (size_t)blockIdx.z * K * N;
    const float* inz = in + zo;
    __half* outz = out + zo;
    const float* scz = sc ? sc + (size_t)blockIdx.z * K : nullptr;
    int nb = blockIdx.x * 32, kb = blockIdx.y * 32;
    int tx = threadIdx.x, ty = threadIdx.y;
#pragma unroll
    for (int i = 0; i < 4; i++) {
        int k = kb + ty + i * 8;
        float v = inz[(size_t)k * N + nb + tx];
        if (scz) v *= scz[k];
        t[ty + i * 8][tx] = v;
    }
    __syncthreads();
#pragma unroll
    for (int i = 0; i < 4; i++)
        outz[(size_t)(nb + ty + i * 8) * K + kb + tx] = __float2half(t[tx][ty + i * 8]);
}

// ---------------------------------------------------------------------------
// fused Wkv transpose: in[z][1024][2048] fp32 -> outS (scaled by sc[z][k]) and
// outP (plain), both [z][2048][1024] half. Read once, write twice.
// ---------------------------------------------------------------------------
__global__ void transkv_kernel(const float* __restrict__ in, __half* __restrict__ outS,
                               __half* __restrict__ outP, const float* __restrict__ sc)
{
    __shared__ float t[32][33];
    __shared__ float scs[32];
    const size_t zo = (size_t)blockIdx.z * 2097152;
    const float* inz = in + zo;
    __half* oS = outS + zo;
    __half* oP = outP + zo;
    int nb = blockIdx.x * 32, kb = blockIdx.y * 32;
    int tx = threadIdx.x, ty = threadIdx.y;
    if (ty == 0) scs[tx] = sc[blockIdx.z * 1024 + kb + tx];
#pragma unroll
    for (int i = 0; i < 4; i++) {
        int k = kb + ty + i * 8;
        t[ty + i * 8][tx] = inz[(size_t)k * 2048 + nb + tx];
    }
    __syncthreads();
#pragma unroll
    for (int i = 0; i < 4; i++) {
        size_t oi = (size_t)(nb + ty + i * 8) * 1024 + kb + tx;
        float v = t[tx][ty + i * 8];
        oP[oi] = __float2half(v);
        oS[oi] = __float2half(v * scs[tx]);
    }
}

// ---------------------------------------------------------------------------
__global__ void gemv_bias_kernel(const float* __restrict__ b, const float* __restrict__ W,
                                 float* __restrict__ bias, int N)
{
    int j = blockIdx.x * 256 + threadIdx.x;
    const float* Wz = W + (size_t)blockIdx.y * 1024 * N;
    const float* bz = b + (size_t)blockIdx.y * 1024;
    float s = 0.f;
    for (int k = 0; k < 1024; k++) s += bz[k] * Wz[(size_t)k * N + j];
    bias[blockIdx.y * N + j] = s;
}

// ---------------------------------------------------------------------------
// Attention on fp16 mma: block = (b,h), 128 threads = 4 warps, warp owns 16
// query rows. 64-key chunks, online softmax on fragments, P re-packed in
// registers for PV. KX row stride 4096 (fused layers), KL stride 2048.
// ---------------------------------------------------------------------------
#define SMEM_ATT (3 * 64 * 72 * 2)

__global__ __launch_bounds__(128) void attn_kernel(
    const __half* __restrict__ Q, const __half* __restrict__ KX,
    const __half* __restrict__ KL, __half* __restrict__ O)
{
    extern __shared__ __align__(16) __half sa[];
    __half* qs = sa;
    __half* ks = sa + 64 * 72;
    __half* vs = sa + 2 * 64 * 72;

    const int bh = blockIdx.x, b = bh >> 4, h = bh & 15;
    const int tid = threadIdx.x, wid = tid >> 5, lane = tid & 31;
    const int gid = lane >> 2, tg = lane & 3;
    const int row0 = wid * 16 + gid;

    {
        const __half2 sc2 = __floats2half2_rn(0.125f, 0.125f);
        const __half* Qb = Q + ((size_t)b * 64) * 1024 + h * 64;
        for (int i = tid; i < 2048; i += 128) {
            int r = i >> 5, cc = i & 31;
            __half2 v = *(const __half2*)(Qb + (size_t)r * 1024 + cc * 2);
            *(__half2*)(qs + r * 72 + cc * 2) = __hmul2(v, sc2);
        }
    }

    float m0 = -1e30f, m1 = -1e30f, l0 = 0.f, l1 = 0.f;
    float oa[8][4];
#pragma unroll
    for (int ni = 0; ni < 8; ni++)
#pragma unroll
        for (int j = 0; j < 4; j++) oa[ni][j] = 0.f;

    for (int c = 0; c < 33; c++) {
        __syncthreads();
        const __half* base;
        size_t ld;
        if (c < 32) { base = KX + ((size_t)(b * 2048 + c * 64)) * 4096 + h * 64; ld = 4096; }
        else        { base = KL + ((size_t)(b * 64)) * 2048 + h * 64;            ld = 2048; }
        for (int i = tid; i < 512; i += 128) {
            int r = i >> 3, cc = i & 7;
            *(uint4*)(ks + r * 72 + cc * 8) = *(const uint4*)(base + (size_t)r * ld + cc * 8);
        }
        for (int i = tid; i < 512; i += 128) {
            int r = i >> 3, cc = i & 7;
            uint4 v4 = *(const uint4*)(base + (size_t)r * ld + 1024 + cc * 8);
            const __half* hv = (const __half*)&v4;
#pragma unroll
            for (int j = 0; j < 8; j++) vs[(cc * 8 + j) * 72 + r] = hv[j];
        }
        __syncthreads();

        float sc[8][4];
#pragma unroll
        for (int ni = 0; ni < 8; ni++)
#pragma unroll
            for (int j = 0; j < 4; j++) sc[ni][j] = 0.f;
#pragma unroll
        for (int kk = 0; kk < 4; kk++) {
            const int k0 = kk << 4;
            const __half* ap = qs + row0 * 72 + k0 + 2 * tg;
            uint32_t a0 = *(const uint32_t*)(ap);
            uint32_t a1 = *(const uint32_t*)(ap + 8 * 72);
            uint32_t a2 = *(const uint32_t*)(ap + 8);
            uint32_t a3 = *(const uint32_t*)(ap + 8 * 72 + 8);
#pragma unroll
            for (int ni = 0; ni < 8; ni++) {
                const __half* bp = ks + (ni * 8 + gid) * 72 + k0 + 2 * tg;
                uint32_t b0 = *(const uint32_t*)(bp);
                uint32_t b1 = *(const uint32_t*)(bp + 8);
                MMA16816(sc[ni], a0, a1, a2, a3, b0, b1);
            }
        }

        float mx0 = -1e30f, mx1 = -1e30f;
#pragma unroll
        for (int ni = 0; ni < 8; ni++) {
            mx0 = fmaxf(mx0, fmaxf(sc[ni][0], sc[ni][1]));
            mx1 = fmaxf(mx1, fmaxf(sc[ni][2], sc[ni][3]));
        }
        mx0 = fmaxf(mx0, __shfl_xor_sync(0xffffffffu, mx0, 1));
        mx0 = fmaxf(mx0, __shfl_xor_sync(0xffffffffu, mx0, 2));
        mx1 = fmaxf(mx1, __shfl_xor_sync(0xffffffffu, mx1, 1));
        mx1 = fmaxf(mx1, __shfl_xor_sync(0xffffffffu, mx1, 2));
        float mn0 = fmaxf(m0, mx0), mn1 = fmaxf(m1, mx1);
        float al0 = __expf(m0 - mn0), al1 = __expf(m1 - mn1);

        uint32_t pa[8][2];
        float ps0 = 0.f, ps1 = 0.f;
#pragma unroll
        for (int ni = 0; ni < 8; ni++) {
            float p0 = __expf(sc[ni][0] - mn0), p1 = __expf(sc[ni][1] - mn0);
            float p2 = __expf(sc[ni][2] - mn1), p3 = __expf(sc[ni][3] - mn1);
            ps0 += p0 + p1; ps1 += p2 + p3;
            __half2 h0 = __floats2half2_rn(p0, p1);
            __half2 h1 = __floats2half2_rn(p2, p3);
            pa[ni][0] = *(uint32_t*)&h0;
            pa[ni][1] = *(uint32_t*)&h1;
        }
        ps0 += __shfl_xor_sync(0xffffffffu, ps0, 1);
        ps0 += __shfl_xor_sync(0xffffffffu, ps0, 2);
        ps1 += __shfl_xor_sync(0xffffffffu, ps1, 1);
        ps1 += __shfl_xor_sync(0xffffffffu, ps1, 2);
        l0 = l0 * al0 + ps0; l1 = l1 * al1 + ps1;
        m0 = mn0; m1 = mn1;
#pragma unroll
        for (int ni = 0; ni < 8; ni++) {
            oa[ni][0] *= al0; oa[ni][1] *= al0;
            oa[ni][2] *= al1; oa[ni][3] *= al1;
        }

#pragma unroll
        for (int kk = 0; kk < 4; kk++) {
            uint32_t a0 = pa[2 * kk][0],     a1 = pa[2 * kk][1];
            uint32_t a2 = pa[2 * kk + 1][0], a3 = pa[2 * kk + 1][1];
#pragma unroll
            for (int ni = 0; ni < 8; ni++) {
                const __half* bp = vs + (ni * 8 + gid) * 72 + (kk << 4) + 2 * tg;
                uint32_t b0 = *(const uint32_t*)(bp);
                uint32_t b1 = *(const uint32_t*)(bp + 8);
                MMA16816(oa[ni], a0, a1, a2, a3, b0, b1);
            }
        }
    }

    float inv0 = 1.0f / l0, inv1 = 1.0f / l1;
    __half* Ob0 = O + ((size_t)(b * 64 + row0)) * 1024 + h * 64;
    __half* Ob1 = Ob0 + 8 * 1024;
#pragma unroll
    for (int ni = 0; ni < 8; ni++) {
        *(__half2*)(Ob0 + ni * 8 + 2 * tg) = __floats2half2_rn(oa[ni][0] * inv0, oa[ni][1] * inv0);
        *(__half2*)(Ob1 + ni * 8 + 2 * tg) = __floats2half2_rn(oa[ni][2] * inv1, oa[ni][3] * inv1);
    }
}

// ---------------------------------------------------------------------------
// Launch.  Order matters for ncu (-s 5 -c 1): launch index 5 = kvX tc_gemm.
// ---------------------------------------------------------------------------
extern "C" void kernel_launch(void* const* d_in, const int* in_sizes, int n_in,
                              void* d_out, int out_size)
{
    const float* x       = (const float*)d_in[0];
    const float* latents = (const float*)d_in[1];
    const float* n1s     = (const float*)d_in[2];
    const float* n1b     = (const float*)d_in[3];
    const float* n2s     = (const float*)d_in[4];
    const float* n2b     = (const float*)d_in[5];
    const float* Wq      = (const float*)d_in[6];
    const float* Wkv     = (const float*)d_in[7];
    const float* Wo      = (const float*)d_in[8];
    const float* ffs     = (const float*)d_in[9];
    const float* ffb     = (const float*)d_in[10];
    const float* W1      = (const float*)d_in[11];
    const float* W2      = (const float*)d_in[12];
    const float* projw   = (const float*)d_in[13];
    const float* projb   = (const float*)d_in[14];
    const float* outs    = (const float*)d_in[15];
    const float* outb    = (const float*)d_in[16];
    float* out = (float*)d_out;

    __half *z, *kvX, *kvL, *latH, *ltn, *q, *o, *hbuf;
    __half *WqT, *WoT, *prT, *WkvTs, *WkvTp, *W1T, *W2T;
    float *lat, *t2, *bkv;
    cudaGetSymbolAddress((void**)&z,    g_z);
    cudaGetSymbolAddress((void**)&kvX,  g_kvX);
    cudaGetSymbolAddress((void**)&kvL,  g_kvL);
    cudaGetSymbolAddress((void**)&lat,  g_lat);
    cudaGetSymbolAddress((void**)&latH, g_latH);
    cudaGetSymbolAddress((void**)&ltn,  g_ltn);
    cudaGetSymbolAddress((void**)&q,    g_q);
    cudaGetSymbolAddress((void**)&o,    g_o);
    cudaGetSymbolAddress((void**)&t2,   g_t2);
    cudaGetSymbolAddress((void**)&hbuf, g_h);
    cudaGetSymbolAddress((void**)&WqT,  g_WqT);
    cudaGetSymbolAddress((void**)&WoT,  g_WoT);
    cudaGetSymbolAddress((void**)&prT,  g_prT);
    cudaGetSymbolAddress((void**)&WkvTs,g_WkvTs);
    cudaGetSymbolAddress((void**)&WkvTp,g_WkvTp);
    cudaGetSymbolAddress((void**)&W1T,  g_W1T);
    cudaGetSymbolAddress((void**)&W2T,  g_W2T);
    cudaGetSymbolAddress((void**)&bkv,  g_bkv);

    cudaFuncSetAttribute(tc_gemm, cudaFuncAttributeMaxDynamicSharedMemorySize, SMEM_TC);
    cudaFuncSetAttribute(attn_kernel, cudaFuncAttributeMaxDynamicSharedMemorySize, SMEM_ATT);

    dim3 tb(32, 8);

    // launch 0-4: minimal deps for kvX
    bcast_kernel<<<8192, 256>>>(latents, lat);                               // 0
    lnw_kernel<<<16384, 128>>>(x, nullptr, z, nullptr, nullptr);             // 1
    transkv_kernel<<<dim3(64, 32, 2), tb>>>(Wkv, WkvTs, WkvTp, n1s);         // 2
    gemv_bias_kernel<<<dim3(8, 2), 256>>>(n1b, Wkv, bkv, 2048);              // 3
    transpose_kernel<<<dim3(32, 32, 2), tb>>>(Wq, WqT, 1024, 1024, nullptr); // 4

    // launch 5: THE dominant kernel (ncu -s 5 captures this)
    tc_gemm<<<dim3(32, 512), 128, SMEM_TC>>>(z, WkvTs,
        nullptr, bkv, nullptr, kvX, 65536, 4096, 1024, F_HALF);              // 5

    // remaining prep
    transpose_kernel<<<dim3(32, 32, 2), tb>>>(Wo, WoT, 1024, 1024, nullptr);
    transpose_kernel<<<dim3(128,32, 2), tb>>>(W1, W1T, 1024, 4096, nullptr);
    transpose_kernel<<<dim3(32,128, 2), tb>>>(W2, W2T, 4096, 1024, nullptr);
    transpose_kernel<<<dim3(32, 32, 1), tb>>>(projw, prT, 1024, 1024, nullptr);

    // ---- layers ----
    for (int i = 0; i < 2; i++) {
        lnw_kernel<<<512, 128>>>(lat, nullptr, ltn, n2s + i*1024, n2b + i*1024);

        tc_gemm<<<dim3(8, 16), 128, SMEM_TC>>>(ltn, WqT + (size_t)i*1048576,
            nullptr, nullptr, nullptr, q, 2048, 1024, 1024, F_HALF);
        tc_gemm<<<dim3(16, 16), 128, SMEM_TC>>>(ltn, WkvTp + (size_t)i*2097152,
            nullptr, nullptr, nullptr, kvL, 2048, 2048, 1024, F_HALF);

        attn_kernel<<<512, 128, SMEM_ATT>>>(q, kvX + (size_t)i * 2048, kvL, o);

        tc_gemm<<<dim3(8, 16), 128, SMEM_TC>>>(o, WoT + (size_t)i*1048576,
            lat, nullptr, lat, nullptr, 2048, 1024, 1024, F_RES);
        lnw_kernel<<<512, 128>>>(lat, nullptr, ltn, ffs + i*1024, ffb + i*1024);
        tc_gemm<<<dim3(32, 16), 128, SMEM_TC>>>(ltn, W1T + (size_t)i*4194304,
            nullptr, nullptr, nullptr, hbuf, 2048, 4096, 1024, F_GELU | F_HALF);
        // layer 1: also emit latH for the projection GEMM (saves f2h pass)
        tc_gemm<<<dim3(8, 16), 128, SMEM_TC>>>(hbuf, W2T + (size_t)i*4194304,
            lat, nullptr, lat, latH, 2048, 1024, 4096,
            F_RES | (i == 1 ? F_BOTH : 0));
    }

    // out = LN(lat @ proj_w + proj_b)
    tc_gemm<<<dim3(8, 16), 128, SMEM_TC>>>(latH, prT, nullptr, projb, t2, nullptr,
                                           2048, 1024, 1024, 0);
    lnw_kernel<<<512, 128>>>(t2, out, nullptr, outs, outb);
}

// round 11
// speedup vs baseline: 7.3313x; 1.1121x over previous
#include <cuda_runtime.h>
#include <cuda_fp16.h>
#include <cstdint>
#include <math.h>

// B=32, N1=2048, DIM=1024, HEADS=16, DH=64, NQ=64, L=2, FF=4096
#define F_RES  1
#define F_GELU 4
#define F_HALF 8
#define F_BOTH 16

// ---- scratch (device globals; allocation-free rule) ----
__device__ __half g_z   [67108864];   // 65536 x 1024  unit-LN(x)
__device__ __half g_kvX [268435456];  // 65536 x 4096  (both layers fused)
__device__ __half g_kvL [4194304];    // 2048  x 2048
__device__ float  g_lat [2097152];
__device__ __half g_latH[2097152];
__device__ __half g_ltn [2097152];
__device__ __half g_q   [2097152];
__device__ __half g_o   [2097152];
__device__ float  g_t2  [2097152];
__device__ __half g_h   [8388608];    // 2048 x 4096
__device__ __half g_WqT [2097152];    // 2 x [1024][1024]  ([N][K])
__device__ __half g_WoT [2097152];
__device__ __half g_prT [1048576];
__device__ __half g_WkvTs[4194304];   // [4096][1024] scaled by norm1_s (2 layers)
__device__ __half g_WkvTp[4194304];
__device__ __half g_W1T [8388608];
__device__ __half g_W2T [8388608];
__device__ float  g_bkv [4096];

// ---------------------------------------------------------------------------
__device__ __forceinline__ uint32_t s2u(const void* p) {
    return (uint32_t)__cvta_generic_to_shared(p);
}
__device__ __forceinline__ void cpasync16(uint32_t dst, const void* src) {
    asm volatile("cp.async.cg.shared.global [%0], [%1], 16;" :: "r"(dst), "l"(src) : "memory");
}
__device__ __forceinline__ float gelu_f(float x) {
    float x3 = x * x * x;
    return 0.5f * x * (1.0f + tanhf(0.7978845608028654f * (x + 0.044715f * x3)));
}
#define MMA16816(c, a0, a1, a2, a3, b0, b1) \
    asm volatile( \
        "mma.sync.aligned.m16n8k16.row.col.f32.f16.f16.f32 " \
        "{%0,%1,%2,%3}, {%4,%5,%6,%7}, {%8,%9}, {%0,%1,%2,%3};" \
        : "+f"((c)[0]), "+f"((c)[1]), "+f"((c)[2]), "+f"((c)[3]) \
        : "r"(a0), "r"(a1), "r"(a2), "r"(a3), "r"(b0), "r"(b1))

// ---------------------------------------------------------------------------
// fp16 mma GEMM: C[M,N] = A[M,K] @ Bt[N,K]^T  (+bias/gelu/residual)
// BM=128, BN=128, BK=64, 4 warps (2x2), warp tile 64x64, m16n8k16,
// 3-stage cp.async pipeline, 2 CTAs/SM. K % 64 == 0, K >= 192.
// ---------------------------------------------------------------------------
#define AS_H      72                   // halves per smem row (144B stride)
#define TILE_H    (128 * AS_H)         // 9216 halves per operand tile
#define STG_H     (2 * TILE_H)
#define SMEM_TC   (3 * STG_H * 2)      // 110592 bytes

__device__ __forceinline__ void load_tile(
    __half* sm, int s, const __half* __restrict__ A, const __half* __restrict__ Bt,
    int K, size_t rowBase, size_t colBase, int t, int tid)
{
    __half* As = sm + s * STG_H;
    __half* Bs = As + TILE_H;
    const __half* Ag = A  + rowBase * K + t * 64;
    const __half* Bg = Bt + colBase * K + t * 64;
#pragma unroll
    for (int i = 0; i < 8; i++) {                 // A: 128 rows x 8 chunks(16B)
        int ch = tid + (i << 7);                  // 0..1023
        int r = ch >> 3, c = ch & 7;
        cpasync16(s2u(As + r * AS_H + c * 8), Ag + (size_t)r * K + c * 8);
    }
#pragma unroll
    for (int i = 0; i < 8; i++) {                 // B: 128 rows x 8 chunks(16B)
        int ch = tid + (i << 7);
        int r = ch >> 3, c = ch & 7;
        cpasync16(s2u(Bs + r * AS_H + c * 8), Bg + (size_t)r * K + c * 8);
    }
    asm volatile("cp.async.commit_group;" ::: "memory");
}

__global__ __launch_bounds__(128, 2) void tc_gemm(
    const __half* __restrict__ A, const __half* __restrict__ Bt,
    const float* __restrict__ Cin, const float* __restrict__ bias,
    float* __restrict__ C, __half* __restrict__ Ch,
    int M, int N, int K, int flags)
{
    extern __shared__ __align__(16) __half sm[];
    const int tid = threadIdx.x, wid = tid >> 5, lane = tid & 31;
    const int wm = wid & 1, wn = wid >> 1;
    const int gid = lane >> 2, tg = lane & 3;
    const size_t rowBase = (size_t)blockIdx.y * 128;
    const size_t colBase = (size_t)blockIdx.x * 128;

    float c[4][8][4];
#pragma unroll
    for (int mi = 0; mi < 4; mi++)
#pragma unroll
        for (int ni = 0; ni < 8; ni++)
#pragma unroll
            for (int k = 0; k < 4; k++) c[mi][ni][k] = 0.f;

    const int KT = K >> 6;
#pragma unroll
    for (int t = 0; t < 2; t++) load_tile(sm, t, A, Bt, K, rowBase, colBase, t, tid);

    for (int t = 0; t < KT; t++) {
        const int s = t % 3;
        asm volatile("cp.async.wait_group 1;" ::: "memory");
        __syncthreads();
        const int tp = t + 2;
        if (tp < KT) load_tile(sm, tp % 3, A, Bt, K, rowBase, colBase, tp, tid);

        const __half* As = sm + s * STG_H;
        const __half* Bs = As + TILE_H;
#pragma unroll
        for (int ks = 0; ks < 4; ks++) {
            const int k0 = ks << 4;
            uint32_t a[4][4], b[8][2];
#pragma unroll
            for (int mi = 0; mi < 4; mi++) {
                const __half* ap = As + (wm * 64 + mi * 16 + gid) * AS_H + k0 + 2 * tg;
                a[mi][0] = *(const uint32_t*)(ap);
                a[mi][1] = *(const uint32_t*)(ap + 8 * AS_H);
                a[mi][2] = *(const uint32_t*)(ap + 8);
                a[mi][3] = *(const uint32_t*)(ap + 8 * AS_H + 8);
            }
#pragma unroll
            for (int ni = 0; ni < 8; ni++) {
                const __half* bp = Bs + (wn * 64 + ni * 8 + gid) * AS_H + k0 + 2 * tg;
                b[ni][0] = *(const uint32_t*)(bp);
                b[ni][1] = *(const uint32_t*)(bp + 8);
            }
#pragma unroll
            for (int mi = 0; mi < 4; mi++)
#pragma unroll
                for (int ni = 0; ni < 8; ni++)
                    MMA16816(c[mi][ni], a[mi][0], a[mi][1], a[mi][2], a[mi][3],
                             b[ni][0], b[ni][1]);
        }
    }

    // epilogue
#pragma unroll
    for (int mi = 0; mi < 4; mi++) {
        const size_t r0 = rowBase + wm * 64 + mi * 16 + gid;
        const size_t r1 = r0 + 8;
#pragma unroll
        for (int ni = 0; ni < 8; ni++) {
            const size_t col = colBase + wn * 64 + ni * 8 + tg * 2;
            float v0 = c[mi][ni][0], v1 = c[mi][ni][1];
            float v2 = c[mi][ni][2], v3 = c[mi][ni][3];
            if (bias) {
                float b0 = bias[col], b1 = bias[col + 1];
                v0 += b0; v1 += b1; v2 += b0; v3 += b1;
            }
            if (flags & F_GELU) {
                v0 = gelu_f(v0); v1 = gelu_f(v1); v2 = gelu_f(v2); v3 = gelu_f(v3);
            }
            if (flags & F_RES) {
                const float2 p0 = *(const float2*)(Cin + r0 * N + col);
                const float2 p1 = *(const float2*)(Cin + r1 * N + col);
                v0 += p0.x; v1 += p0.y; v2 += p1.x; v3 += p1.y;
            }
            if (flags & F_HALF) {
                *(__half2*)(Ch + r0 * N + col) = __floats2half2_rn(v0, v1);
                *(__half2*)(Ch + r1 * N + col) = __floats2half2_rn(v2, v3);
            } else {
                *(float2*)(C + r0 * N + col) = make_float2(v0, v1);
                *(float2*)(C + r1 * N + col) = make_float2(v2, v3);
                if (flags & F_BOTH) {
                    *(__half2*)(Ch + r0 * N + col) = __floats2half2_rn(v0, v1);
                    *(__half2*)(Ch + r1 * N + col) = __floats2half2_rn(v2, v3);
                }
            }
        }
    }
}

// ---------------------------------------------------------------------------
__global__ void bcast_kernel(const float* __restrict__ lat0, float* __restrict__ lat)
{
    int i = blockIdx.x * 256 + threadIdx.x;
    lat[i] = lat0[i & 65535];
}

// ---------------------------------------------------------------------------
// Warp-per-row LayerNorm over 1024 cols. 128 threads = 4 rows/block.
// ---------------------------------------------------------------------------
__global__ __launch_bounds__(128) void lnw_kernel(
    const float* __restrict__ in, float* __restrict__ outF, __half* __restrict__ outH,
    const float* __restrict__ gs, const float* __restrict__ gb)
{
    const int row = blockIdx.x * 4 + (threadIdx.x >> 5);
    const int lane = threadIdx.x & 31;
    const float4* ip = (const float4*)(in + (size_t)row * 1024);

    float4 v[8];
    float s = 0.f, s2 = 0.f;
#pragma unroll
    for (int j = 0; j < 8; j++) {
        v[j] = ip[lane + 32 * j];
        s  += v[j].x + v[j].y + v[j].z + v[j].w;
        s2 += v[j].x*v[j].x + v[j].y*v[j].y + v[j].z*v[j].z + v[j].w*v[j].w;
    }
#pragma unroll
    for (int o = 16; o; o >>= 1) {
        s  += __shfl_xor_sync(0xffffffffu, s,  o);
        s2 += __shfl_xor_sync(0xffffffffu, s2, o);
    }
    const float mean = s * (1.0f / 1024.0f);
    const float inv  = rsqrtf(s2 * (1.0f / 1024.0f) - mean * mean + 1e-5f);

#pragma unroll
    for (int j = 0; j < 8; j++) {
        const int idx = lane + 32 * j;
        float4 ov;
        ov.x = (v[j].x - mean) * inv; ov.y = (v[j].y - mean) * inv;
        ov.z = (v[j].z - mean) * inv; ov.w = (v[j].w - mean) * inv;
        if (gs) {
            const float4 sv = ((const float4*)gs)[idx];
            const float4 bv = ((const float4*)gb)[idx];
            ov.x = ov.x * sv.x + bv.x; ov.y = ov.y * sv.y + bv.y;
            ov.z = ov.z * sv.z + bv.z; ov.w = ov.w * sv.w + bv.w;
        }
        if (outH) {
            __half2 h0 = __floats2half2_rn(ov.x, ov.y);
            __half2 h1 = __floats2half2_rn(ov.z, ov.w);
            uint2 pk;
            pk.x = *(uint32_t*)&h0; pk.y = *(uint32_t*)&h1;
            ((uint2*)(outH + (size_t)row * 1024))[idx] = pk;
        } else {
            ((float4*)(outF + (size_t)row * 1024))[idx] = ov;
        }
    }
}

// ---------------------------------------------------------------------------
// transpose (batched over gridDim.z): in[z][K][N] fp32 -> out[z][N][K] half
// ---------------------------------------------------------------------------
__global__ void transpose_kernel(const float* __restrict__ in, __half* __restrict__ out,
                                 int K, int N, const float* __restrict__ sc)
{
    __shared__ float t[32][33];
    const size_t zo = (size_t)blockIdx.z * K * N;
    const float* inz = in + zo;
    __half* outz = out + zo;
    const float* scz = sc ? sc + (size_t)blockIdx.z * K : nullptr;
    int nb = blockIdx.x * 32, kb = blockIdx.y * 32;
    int tx = threadIdx.x, ty = threadIdx.y;
#pragma unroll
    for (int i = 0; i < 4; i++) {
        int k = kb + ty + i * 8;
        float v = inz[(size_t)k * N + nb + tx];
        if (scz) v *= scz[k];
        t[ty + i * 8][tx] = v;
    }
    __syncthreads();
#pragma unroll
    for (int i = 0; i < 4; i++)
        outz[(size_t)(nb + ty + i * 8) * K + kb + tx] = __float2half(t[tx][ty + i * 8]);
}

// ---------------------------------------------------------------------------
// fused Wkv transpose: read once, write scaled + plain
// ---------------------------------------------------------------------------
__global__ void transkv_kernel(const float* __restrict__ in, __half* __restrict__ outS,
                               __half* __restrict__ outP, const float* __restrict__ sc)
{
    __shared__ float t[32][33];
    __shared__ float scs[32];
    const size_t zo = (size_t)blockIdx.z * 2097152;
    const float* inz = in + zo;
    __half* oS = outS + zo;
    __half* oP = outP + zo;
    int nb = blockIdx.x * 32, kb = blockIdx.y * 32;
    int tx = threadIdx.x, ty = threadIdx.y;
    if (ty == 0) scs[tx] = sc[blockIdx.z * 1024 + kb + tx];
#pragma unroll
    for (int i = 0; i < 4; i++) {
        int k = kb + ty + i * 8;
        t[ty + i * 8][tx] = inz[(size_t)k * 2048 + nb + tx];
    }
    __syncthreads();
#pragma unroll
    for (int i = 0; i < 4; i++) {
        size_t oi = (size_t)(nb + ty + i * 8) * 1024 + kb + tx;
        float v = t[tx][ty + i * 8];
        oP[oi] = __float2half(v);
        oS[oi] = __float2half(v * scs[tx]);
    }
}

// ---------------------------------------------------------------------------
// bias fold, warp-per-output: bias[j] = sum_k b[j/2048][k] * WkvTp[j][k]
// ---------------------------------------------------------------------------
__global__ __launch_bounds__(128) void gemv_bias_kernel(
    const float* __restrict__ b, const __half* __restrict__ WT,
    float* __restrict__ bias)
{
    const int j = blockIdx.x * 4 + (threadIdx.x >> 5);   // 0..4095
    const int lane = threadIdx.x & 31;
    const float* bz = b + (j >> 11) * 1024;
    const __half* wp = WT + (size_t)j * 1024;

    float s = 0.f;
#pragma unroll
    for (int i = 0; i < 4; i++) {
        uint4 w8 = ((const uint4*)wp)[lane + 32 * i];
        const __half2* hw = (const __half2*)&w8;
        const int k0 = (lane + 32 * i) * 8;
#pragma unroll
        for (int p = 0; p < 4; p++) {
            float2 wf = __half22float2(hw[p]);
            s += wf.x * bz[k0 + 2 * p] + wf.y * bz[k0 + 2 * p + 1];
        }
    }
#pragma unroll
    for (int o = 16; o; o >>= 1) s += __shfl_xor_sync(0xffffffffu, s, o);
    if (lane == 0) bias[j] = s;
}

// ---------------------------------------------------------------------------
// Attention on fp16 mma (validated in R7-R9)
// ---------------------------------------------------------------------------
#define SMEM_ATT (3 * 64 * 72 * 2)

__global__ __launch_bounds__(128) void attn_kernel(
    const __half* __restrict__ Q, const __half* __restrict__ KX,
    const __half* __restrict__ KL, __half* __restrict__ O)
{
    extern __shared__ __align__(16) __half sa[];
    __half* qs = sa;
    __half* ks = sa + 64 * 72;
    __half* vs = sa + 2 * 64 * 72;

    const int bh = blockIdx.x, b = bh >> 4, h = bh & 15;
    const int tid = threadIdx.x, wid = tid >> 5, lane = tid & 31;
    const int gid = lane >> 2, tg = lane & 3;
    const int row0 = wid * 16 + gid;

    {
        const __half2 sc2 = __floats2half2_rn(0.125f, 0.125f);
        const __half* Qb = Q + ((size_t)b * 64) * 1024 + h * 64;
        for (int i = tid; i < 2048; i += 128) {
            int r = i >> 5, cc = i & 31;
            __half2 v = *(const __half2*)(Qb + (size_t)r * 1024 + cc * 2);
            *(__half2*)(qs + r * 72 + cc * 2) = __hmul2(v, sc2);
        }
    }

    float m0 = -1e30f, m1 = -1e30f, l0 = 0.f, l1 = 0.f;
    float oa[8][4];
#pragma unroll
    for (int ni = 0; ni < 8; ni++)
#pragma unroll
        for (int j = 0; j < 4; j++) oa[ni][j] = 0.f;

    for (int c = 0; c < 33; c++) {
        __syncthreads();
        const __half* base;
        size_t ld;
        if (c < 32) { base = KX + ((size_t)(b * 2048 + c * 64)) * 4096 + h * 64; ld = 4096; }
        else        { base = KL + ((size_t)(b * 64)) * 2048 + h * 64;            ld = 2048; }
        for (int i = tid; i < 512; i += 128) {
            int r = i >> 3, cc = i & 7;
            *(uint4*)(ks + r * 72 + cc * 8) = *(const uint4*)(base + (size_t)r * ld + cc * 8);
        }
        for (int i = tid; i < 512; i += 128) {
            int r = i >> 3, cc = i & 7;
            uint4 v4 = *(const uint4*)(base + (size_t)r * ld + 1024 + cc * 8);
            const __half* hv = (const __half*)&v4;
#pragma unroll
            for (int j = 0; j < 8; j++) vs[(cc * 8 + j) * 72 + r] = hv[j];
        }
        __syncthreads();

        float sc[8][4];
#pragma unroll
        for (int ni = 0; ni < 8; ni++)
#pragma unroll
            for (int j = 0; j < 4; j++) sc[ni][j] = 0.f;
#pragma unroll
        for (int kk = 0; kk < 4; kk++) {
            const int k0 = kk << 4;
            const __half* ap = qs + row0 * 72 + k0 + 2 * tg;
            uint32_t a0 = *(const uint32_t*)(ap);
            uint32_t a1 = *(const uint32_t*)(ap + 8 * 72);
            uint32_t a2 = *(const uint32_t*)(ap + 8);
            uint32_t a3 = *(const uint32_t*)(ap + 8 * 72 + 8);
#pragma unroll
            for (int ni = 0; ni < 8; ni++) {
                const __half* bp = ks + (ni * 8 + gid) * 72 + k0 + 2 * tg;
                uint32_t b0 = *(const uint32_t*)(bp);
                uint32_t b1 = *(const uint32_t*)(bp + 8);
                MMA16816(sc[ni], a0, a1, a2, a3, b0, b1);
            }
        }

        float mx0 = -1e30f, mx1 = -1e30f;
#pragma unroll
        for (int ni = 0; ni < 8; ni++) {
            mx0 = fmaxf(mx0, fmaxf(sc[ni][0], sc[ni][1]));
            mx1 = fmaxf(mx1, fmaxf(sc[ni][2], sc[ni][3]));
        }
        mx0 = fmaxf(mx0, __shfl_xor_sync(0xffffffffu, mx0, 1));
        mx0 = fmaxf(mx0, __shfl_xor_sync(0xffffffffu, mx0, 2));
        mx1 = fmaxf(mx1, __shfl_xor_sync(0xffffffffu, mx1, 1));
        mx1 = fmaxf(mx1, __shfl_xor_sync(0xffffffffu, mx1, 2));
        float mn0 = fmaxf(m0, mx0), mn1 = fmaxf(m1, mx1);
        float al0 = __expf(m0 - mn0), al1 = __expf(m1 - mn1);

        uint32_t pa[8][2];
        float ps0 = 0.f, ps1 = 0.f;
#pragma unroll
        for (int ni = 0; ni < 8; ni++) {
            float p0 = __expf(sc[ni][0] - mn0), p1 = __expf(sc[ni][1] - mn0);
            float p2 = __expf(sc[ni][2] - mn1), p3 = __expf(sc[ni][3] - mn1);
            ps0 += p0 + p1; ps1 += p2 + p3;
            __half2 h0 = __floats2half2_rn(p0, p1);
            __half2 h1 = __floats2half2_rn(p2, p3);
            pa[ni][0] = *(uint32_t*)&h0;
            pa[ni][1] = *(uint32_t*)&h1;
        }
        ps0 += __shfl_xor_sync(0xffffffffu, ps0, 1);
        ps0 += __shfl_xor_sync(0xffffffffu, ps0, 2);
        ps1 += __shfl_xor_sync(0xffffffffu, ps1, 1);
        ps1 += __shfl_xor_sync(0xffffffffu, ps1, 2);
        l0 = l0 * al0 + ps0; l1 = l1 * al1 + ps1;
        m0 = mn0; m1 = mn1;
#pragma unroll
        for (int ni = 0; ni < 8; ni++) {
            oa[ni][0] *= al0; oa[ni][1] *= al0;
            oa[ni][2] *= al1; oa[ni][3] *= al1;
        }

#pragma unroll
        for (int kk = 0; kk < 4; kk++) {
            uint32_t a0 = pa[2 * kk][0],     a1 = pa[2 * kk][1];
            uint32_t a2 = pa[2 * kk + 1][0], a3 = pa[2 * kk + 1][1];
#pragma unroll
            for (int ni = 0; ni < 8; ni++) {
                const __half* bp = vs + (ni * 8 + gid) * 72 + (kk << 4) + 2 * tg;
                uint32_t b0 = *(const uint32_t*)(bp);
                uint32_t b1 = *(const uint32_t*)(bp + 8);
                MMA16816(oa[ni], a0, a1, a2, a3, b0, b1);
            }
        }
    }

    float inv0 = 1.0f / l0, inv1 = 1.0f / l1;
    __half* Ob0 = O + ((size_t)(b * 64 + row0)) * 1024 + h * 64;
    __half* Ob1 = Ob0 + 8 * 1024;
#pragma unroll
    for (int ni = 0; ni < 8; ni++) {
        *(__half2*)(Ob0 + ni * 8 + 2 * tg) = __floats2half2_rn(oa[ni][0] * inv0, oa[ni][1] * inv0);
        *(__half2*)(Ob1 + ni * 8 + 2 * tg) = __floats2half2_rn(oa[ni][2] * inv1, oa[ni][3] * inv1);
    }
}

// ---------------------------------------------------------------------------
// Launch
// ---------------------------------------------------------------------------
extern "C" void kernel_launch(void* const* d_in, const int* in_sizes, int n_in,
                              void* d_out, int out_size)
{
    const float* x       = (const float*)d_in[0];
    const float* latents = (const float*)d_in[1];
    const float* n1s     = (const float*)d_in[2];
    const float* n1b     = (const float*)d_in[3];
    const float* n2s     = (const float*)d_in[4];
    const float* n2b     = (const float*)d_in[5];
    const float* Wq      = (const float*)d_in[6];
    const float* Wkv     = (const float*)d_in[7];
    const float* Wo      = (const float*)d_in[8];
    const float* ffs     = (const float*)d_in[9];
    const float* ffb     = (const float*)d_in[10];
    const float* W1      = (const float*)d_in[11];
    const float* W2      = (const float*)d_in[12];
    const float* projw   = (const float*)d_in[13];
    const float* projb   = (const float*)d_in[14];
    const float* outs    = (const float*)d_in[15];
    const float* outb    = (const float*)d_in[16];
    float* out = (float*)d_out;

    __half *z, *kvX, *kvL, *latH, *ltn, *q, *o, *hbuf;
    __half *WqT, *WoT, *prT, *WkvTs, *WkvTp, *W1T, *W2T;
    float *lat, *t2, *bkv;
    cudaGetSymbolAddress((void**)&z,    g_z);
    cudaGetSymbolAddress((void**)&kvX,  g_kvX);
    cudaGetSymbolAddress((void**)&kvL,  g_kvL);
    cudaGetSymbolAddress((void**)&lat,  g_lat);
    cudaGetSymbolAddress((void**)&latH, g_latH);
    cudaGetSymbolAddress((void**)&ltn,  g_ltn);
    cudaGetSymbolAddress((void**)&q,    g_q);
    cudaGetSymbolAddress((void**)&o,    g_o);
    cudaGetSymbolAddress((void**)&t2,   g_t2);
    cudaGetSymbolAddress((void**)&hbuf, g_h);
    cudaGetSymbolAddress((void**)&WqT,  g_WqT);
    cudaGetSymbolAddress((void**)&WoT,  g_WoT);
    cudaGetSymbolAddress((void**)&prT,  g_prT);
    cudaGetSymbolAddress((void**)&WkvTs,g_WkvTs);
    cudaGetSymbolAddress((void**)&WkvTp,g_WkvTp);
    cudaGetSymbolAddress((void**)&W1T,  g_W1T);
    cudaGetSymbolAddress((void**)&W2T,  g_W2T);
    cudaGetSymbolAddress((void**)&bkv,  g_bkv);

    cudaFuncSetAttribute(tc_gemm, cudaFuncAttributeMaxDynamicSharedMemorySize, SMEM_TC);
    cudaFuncSetAttribute(attn_kernel, cudaFuncAttributeMaxDynamicSharedMemorySize, SMEM_ATT);

    dim3 tb(32, 8);

    // prep (minimal deps for kvX first)
    bcast_kernel<<<8192, 256>>>(latents, lat);
    lnw_kernel<<<16384, 128>>>(x, nullptr, z, nullptr, nullptr);
    transkv_kernel<<<dim3(64, 32, 2), tb>>>(Wkv, WkvTs, WkvTp, n1s);
    gemv_bias_kernel<<<1024, 128>>>(n1b, WkvTp, bkv);
    transpose_kernel<<<dim3(32, 32, 2), tb>>>(Wq, WqT, 1024, 1024, nullptr);

    // kvX for BOTH layers: [65536][4096]
    tc_gemm<<<dim3(32, 512), 128, SMEM_TC>>>(z, WkvTs,
        nullptr, bkv, nullptr, kvX, 65536, 4096, 1024, F_HALF);

    // remaining prep
    transpose_kernel<<<dim3(32, 32, 2), tb>>>(Wo, WoT, 1024, 1024, nullptr);
    transpose_kernel<<<dim3(128,32, 2), tb>>>(W1, W1T, 1024, 4096, nullptr);
    transpose_kernel<<<dim3(32,128, 2), tb>>>(W2, W2T, 4096, 1024, nullptr);
    transpose_kernel<<<dim3(32, 32, 1), tb>>>(projw, prT, 1024, 1024, nullptr);

    // ---- layers ----
    for (int i = 0; i < 2; i++) {
        lnw_kernel<<<512, 128>>>(lat, nullptr, ltn, n2s + i*1024, n2b + i*1024);

        tc_gemm<<<dim3(8, 16), 128, SMEM_TC>>>(ltn, WqT + (size_t)i*1048576,
            nullptr, nullptr, nullptr, q, 2048, 1024, 1024, F_HALF);
        tc_gemm<<<dim3(16, 16), 128, SMEM_TC>>>(ltn, WkvTp + (size_t)i*2097152,
            nullptr, nullptr, nullptr, kvL, 2048, 2048, 1024, F_HALF);

        attn_kernel<<<512, 128, SMEM_ATT>>>(q, kvX + (size_t)i * 2048, kvL, o);

        tc_gemm<<<dim3(8, 16), 128, SMEM_TC>>>(o, WoT + (size_t)i*1048576,
            lat, nullptr, lat, nullptr, 2048, 1024, 1024, F_RES);
        lnw_kernel<<<512, 128>>>(lat, nullptr, ltn, ffs + i*1024, ffb + i*1024);
        tc_gemm<<<dim3(32, 16), 128, SMEM_TC>>>(ltn, W1T + (size_t)i*4194304,
            nullptr, nullptr, nullptr, hbuf, 2048, 4096, 1024, F_GELU | F_HALF);
        tc_gemm<<<dim3(8, 16), 128, SMEM_TC>>>(hbuf, W2T + (size_t)i*4194304,
            lat, nullptr, lat, latH, 2048, 1024, 4096,
            F_RES | (i == 1 ? F_BOTH : 0));
    }

    // out = LN(lat @ proj_w + proj_b)
    tc_gemm<<<dim3(8, 16), 128, SMEM_TC>>>(latH, prT, nullptr, projb, t2, nullptr,
                                           2048, 1024, 1024, 0);
    lnw_kernel<<<512, 128>>>(t2, out, nullptr, outs, outb);
}